// round 10
// baseline (speedup 1.0000x reference)
#include <cuda_runtime.h>
#include <cstdint>

#define NS 512
#define NC 128
#define ND 640
#define TT 256
#define NBLK 148
#define ASTRIDE 132
#define DSMEM (2 * 128 * ASTRIDE * 4)   // 135168 bytes

// ---------------- persistent device state (no allocation allowed) ----------------
__device__ __align__(16) float g_V[NS * NS];        // carry V (512x512)
__device__ __align__(16) float g_FVp[4][NS * ND];   // FV^T partials [chunk][n(512)][m(640)]
__device__ __align__(16) float g_QP[120][128 * 128];// Q partials [tile*8+chunk]
__device__ __align__(16) float g_Q[ND * ND];        // Q (only needed blocks written)
__device__ __align__(16) float g_K[NC * NS];        // K (128x512)
__device__ __align__(16) float g_X[2][NC * NC];     // Newton ping-pong
__device__ float g_q[ND], g_w[NS], g_v[NS], g_k[NC], g_cst;
__device__ unsigned g_arrive;
__device__ volatile unsigned g_gen;

// Q tile layout: 10 upper-tri xx tiles + 5 u-row tiles
__constant__ int c_tM0[15] = {0, 0, 0, 0, 128, 128, 128, 256, 256, 384, 512, 512, 512, 512, 512};
__constant__ int c_tN0[15] = {0, 128, 256, 384, 128, 256, 384, 256, 384, 384, 0, 128, 256, 384, 512};
__constant__ int c_mir[15] = {0, 1, 1, 1, 0, 1, 1, 0, 1, 0, 0, 0, 0, 0, 0};

// ---------------- grid-wide barrier ----------------------------------------------
__device__ __forceinline__ void gsync() {
    __syncthreads();
    if (threadIdx.x == 0) {
        unsigned gen = g_gen;
        __threadfence();
        if (atomicAdd(&g_arrive, 1u) == gridDim.x - 1) {
            g_arrive = 0;
            __threadfence();
            g_gen = gen + 1;
        } else {
            while (g_gen == gen) { __nanosleep(64); }
        }
        __threadfence();
    }
    __syncthreads();
}

// ---------------- packed f32x2 helpers --------------------------------------------
union UF2 { unsigned long long u; float2 f; };
__device__ __forceinline__ void ffma2(unsigned long long& d,
                                      unsigned long long a, unsigned long long b) {
    asm("fma.rn.f32x2 %0, %1, %2, %0;" : "+l"(d) : "l"(a), "l"(b));
}
__device__ __forceinline__ unsigned long long dup2(float x) {
    unsigned long long r; unsigned xi = __float_as_uint(x);
    asm("mov.b64 %0, {%1, %1};" : "=l"(r) : "r"(xi));
    return r;
}

// ---------------- 128x128 tile core: acc += Astage^T-ish @ Bstage -----------------
// Asrc/Bsrc point at [k][col] layouts, pre-offset to the tile's column window.
// nsum==4: A is the sum of 4 buffers strided by sumstr (FV partial combine on stage).
__device__ __forceinline__ void gemm128_core(
    const float* __restrict__ Asrc, int lda, int nsum, size_t sumstr,
    const float* __restrict__ Bsrc, int ldb, int KC,
    float* sm, UF2 (&acc)[4][8])
{
    float* As = sm;
    float* Bs = sm + 128 * ASTRIDE;
    const int tid = threadIdx.x;
    for (int u = tid; u < KC * 32; u += 256) {
        int kk = u >> 5, c4 = (u & 31) << 2;
        const float* ap = Asrc + (size_t)kk * lda + c4;
        float4 va;
        if (nsum == 4) {
            float4 v0 = *(const float4*)ap;
            float4 v1 = *(const float4*)(ap + sumstr);
            float4 v2 = *(const float4*)(ap + 2 * sumstr);
            float4 v3 = *(const float4*)(ap + 3 * sumstr);
            va.x = (v0.x + v1.x) + (v2.x + v3.x);
            va.y = (v0.y + v1.y) + (v2.y + v3.y);
            va.z = (v0.z + v1.z) + (v2.z + v3.z);
            va.w = (v0.w + v1.w) + (v2.w + v3.w);
        } else {
            va = *(const float4*)ap;
        }
        *(float4*)&As[kk * ASTRIDE + c4] = va;
        *(float4*)&Bs[kk * ASTRIDE + c4] = *(const float4*)(Bsrc + (size_t)kk * ldb + c4);
    }
    __syncthreads();
    const int tx = tid & 15, ty = tid >> 4;
#pragma unroll
    for (int p = 0; p < 4; p++)
#pragma unroll
        for (int j = 0; j < 8; j++) acc[p][j].u = 0ull;
#pragma unroll 2
    for (int kk = 0; kk < KC; kk++) {
        ulonglong2 a01 = *(const ulonglong2*)&As[kk * ASTRIDE + ty * 8];
        ulonglong2 a23 = *(const ulonglong2*)&As[kk * ASTRIDE + ty * 8 + 4];
        float4 b0 = *(const float4*)&Bs[kk * ASTRIDE + tx * 8];
        float4 b1 = *(const float4*)&Bs[kk * ASTRIDE + tx * 8 + 4];
        unsigned long long bd0 = dup2(b0.x), bd1 = dup2(b0.y);
        unsigned long long bd2 = dup2(b0.z), bd3 = dup2(b0.w);
        unsigned long long bd4 = dup2(b1.x), bd5 = dup2(b1.y);
        unsigned long long bd6 = dup2(b1.z), bd7 = dup2(b1.w);
        ffma2(acc[0][0].u, a01.x, bd0); ffma2(acc[0][1].u, a01.x, bd1);
        ffma2(acc[0][2].u, a01.x, bd2); ffma2(acc[0][3].u, a01.x, bd3);
        ffma2(acc[0][4].u, a01.x, bd4); ffma2(acc[0][5].u, a01.x, bd5);
        ffma2(acc[0][6].u, a01.x, bd6); ffma2(acc[0][7].u, a01.x, bd7);
        ffma2(acc[1][0].u, a01.y, bd0); ffma2(acc[1][1].u, a01.y, bd1);
        ffma2(acc[1][2].u, a01.y, bd2); ffma2(acc[1][3].u, a01.y, bd3);
        ffma2(acc[1][4].u, a01.y, bd4); ffma2(acc[1][5].u, a01.y, bd5);
        ffma2(acc[1][6].u, a01.y, bd6); ffma2(acc[1][7].u, a01.y, bd7);
        ffma2(acc[2][0].u, a23.x, bd0); ffma2(acc[2][1].u, a23.x, bd1);
        ffma2(acc[2][2].u, a23.x, bd2); ffma2(acc[2][3].u, a23.x, bd3);
        ffma2(acc[2][4].u, a23.x, bd4); ffma2(acc[2][5].u, a23.x, bd5);
        ffma2(acc[2][6].u, a23.x, bd6); ffma2(acc[2][7].u, a23.x, bd7);
        ffma2(acc[3][0].u, a23.y, bd0); ffma2(acc[3][1].u, a23.y, bd1);
        ffma2(acc[3][2].u, a23.y, bd2); ffma2(acc[3][3].u, a23.y, bd3);
        ffma2(acc[3][4].u, a23.y, bd4); ffma2(acc[3][5].u, a23.y, bd5);
        ffma2(acc[3][6].u, a23.y, bd6); ffma2(acc[3][7].u, a23.y, bd7);
    }
    __syncthreads();
}

// ---------------- 64x64 tile: D = alpha*(A^T-stage @ B) + Cin ---------------------
__device__ __forceinline__ void gemm64_tile(
    const float* __restrict__ Asrc, int lda,
    const float* __restrict__ Bsrc, int ldb,
    const float* __restrict__ Cin, int ldc,
    float* __restrict__ D1, float* __restrict__ D2, int ldd,
    int KC, float alpha, float* sm)
{
    float* As = sm;
    float* Bs = sm + 128 * 68;
    const int tid = threadIdx.x;
    for (int u = tid; u < KC * 16; u += 256) {
        int kk = u >> 4, c4 = (u & 15) << 2;
        *(float4*)&As[kk * 68 + c4] = *(const float4*)(Asrc + (size_t)kk * lda + c4);
        *(float4*)&Bs[kk * 68 + c4] = *(const float4*)(Bsrc + (size_t)kk * ldb + c4);
    }
    __syncthreads();
    const int tx = tid & 15, ty = tid >> 4;
    UF2 acc[2][4];
#pragma unroll
    for (int p = 0; p < 2; p++)
#pragma unroll
        for (int j = 0; j < 4; j++) acc[p][j].u = 0ull;
#pragma unroll 4
    for (int kk = 0; kk < KC; kk++) {
        ulonglong2 ap = *(const ulonglong2*)&As[kk * 68 + ty * 4];
        float4 b = *(const float4*)&Bs[kk * 68 + tx * 4];
        unsigned long long bd0 = dup2(b.x), bd1 = dup2(b.y);
        unsigned long long bd2 = dup2(b.z), bd3 = dup2(b.w);
        ffma2(acc[0][0].u, ap.x, bd0); ffma2(acc[0][1].u, ap.x, bd1);
        ffma2(acc[0][2].u, ap.x, bd2); ffma2(acc[0][3].u, ap.x, bd3);
        ffma2(acc[1][0].u, ap.y, bd0); ffma2(acc[1][1].u, ap.y, bd1);
        ffma2(acc[1][2].u, ap.y, bd2); ffma2(acc[1][3].u, ap.y, bd3);
    }
    __syncthreads();
#pragma unroll
    for (int p = 0; p < 2; p++) {
        int r = ty * 4 + 2 * p;
        float ox[4], oy[4];
#pragma unroll
        for (int j = 0; j < 4; j++) {
            ox[j] = alpha * acc[p][j].f.x;
            oy[j] = alpha * acc[p][j].f.y;
            if (Cin) {
                ox[j] += Cin[(size_t)r * ldc + tx * 4 + j];
                oy[j] += Cin[(size_t)(r + 1) * ldc + tx * 4 + j];
            }
        }
        float4 vx = make_float4(ox[0], ox[1], ox[2], ox[3]);
        float4 vy = make_float4(oy[0], oy[1], oy[2], oy[3]);
        *(float4*)&D1[(size_t)r * ldd + tx * 4] = vx;
        *(float4*)&D1[(size_t)(r + 1) * ldd + tx * 4] = vy;
        if (D2) {
            *(float4*)&D2[(size_t)r * ldd + tx * 4] = vx;
            *(float4*)&D2[(size_t)(r + 1) * ldd + tx * 4] = vy;
        }
    }
}

// ---------------- Newton-Schulz strip (proven in R6) ------------------------------
__device__ __forceinline__ void newton_strip(const float* __restrict__ Xin,
                                             float* __restrict__ Xout, float* sm)
{
    float* Qs = sm;           // [128][20]
    float* Xs = sm + 2560;    // [128][4]
    float* Ts = sm + 3072;    // [128][4]
    const int tid = threadIdx.x;
    const int J = blockIdx.x * 4;
    for (int i = tid; i < 512; i += 256) {
        int r = i >> 2, jj = i & 3;
        Xs[i] = Xin[r * NC + J + jj];
    }
    __syncthreads();
    const int r = tid >> 1, jh = (tid & 1) * 2;
    float t0 = 0.f, t1 = 0.f;
    for (int k0 = 0; k0 < NC; k0 += 16) {
        for (int i = tid; i < 512; i += 256) {
            int rr = i >> 2, q4 = i & 3;
            *(float4*)&Qs[rr * 20 + q4 * 4] =
                *(const float4*)&g_Q[(size_t)(NS + rr) * ND + NS + k0 + q4 * 4];
        }
        __syncthreads();
#pragma unroll
        for (int kk = 0; kk < 16; kk++) {
            float a = Qs[r * 20 + kk];
            t0 = fmaf(a, Xs[(k0 + kk) * 4 + jh], t0);
            t1 = fmaf(a, Xs[(k0 + kk) * 4 + jh + 1], t1);
        }
        __syncthreads();
    }
    Ts[r * 4 + jh] = t0; Ts[r * 4 + jh + 1] = t1;
    __syncthreads();
    float x0 = 0.f, x1 = 0.f;
    for (int k0 = 0; k0 < NC; k0 += 16) {
        for (int i = tid; i < 512; i += 256) {
            int rr = i >> 2, q4 = i & 3;
            *(float4*)&Qs[rr * 20 + q4 * 4] =
                *(const float4*)&Xin[rr * NC + k0 + q4 * 4];
        }
        __syncthreads();
#pragma unroll
        for (int kk = 0; kk < 16; kk++) {
            float a = Qs[r * 20 + kk];
            x0 = fmaf(a, Ts[(k0 + kk) * 4 + jh], x0);
            x1 = fmaf(a, Ts[(k0 + kk) * 4 + jh + 1], x1);
        }
        __syncthreads();
    }
    Xout[r * NC + J + jh]     = 2.f * Xs[r * 4 + jh]     - x0;
    Xout[r * NC + J + jh + 1] = 2.f * Xs[r * 4 + jh + 1] - x1;
}

// ---------------- the persistent kernel -------------------------------------------
__global__ void __launch_bounds__(256, 1) lqr_kernel(
    const float* __restrict__ F, const float* __restrict__ f,
    const float* __restrict__ C, const float* __restrict__ c,
    float* __restrict__ out)
{
    extern __shared__ __align__(16) float smf[];
    __shared__ __align__(16) float sm[3600];
    __shared__ float red[264];
    const int bid = blockIdx.x, tid = threadIdx.x, nb = gridDim.x;
    float* outK = out;
    float* outk = outK + (size_t)TT * NC * NS;
    float* outV = outk + (size_t)TT * NC;
    float* outv = outV + (size_t)TT * NS * NS;
    float* outc = outv + (size_t)TT * NS;

    // ---- init: V = C[:n,:n], v = c[:n], const = 0 ----
    for (int i = bid * 256 + tid; i < NS * NS; i += nb * 256) {
        int r = i >> 9, cq = i & (NS - 1);
        g_V[i] = C[(size_t)r * ND + cq];
    }
    if (bid == nb - 1) {
        for (int i = tid; i < NS; i += 256) g_v[i] = c[i];
        if (tid == 0) g_cst = 0.f;
    }
    gsync();

    int cur = 0;
    for (int s = 0; s < TT; s++) {
        const int t = TT - 1 - s;

        // ---- Phase A: FV^T partials = (Ft @ V)^T, 20 tiles x 4 k-chunks ----
        // As[kk][m] = Ft[m][k0+kk] = F[k0+kk][m]  (coalesced rows of F!)
        if (bid < 80) {
            const int tile = bid >> 2, chunk = bid & 3;
            const int m0 = (tile >> 2) * 128, n0 = (tile & 3) * 128;
            const int k0 = chunk * 128;
            UF2 acc[4][8];
            gemm128_core(F + (size_t)k0 * ND + m0, ND, 0, 0,
                         g_V + (size_t)k0 * NS + n0, NS, 128, smf, acc);
            float* dst = g_FVp[chunk];
            const int tx = tid & 15, ty = tid >> 4;
#pragma unroll
            for (int j = 0; j < 8; j++) {
                int n = n0 + tx * 8 + j;
#pragma unroll
                for (int p = 0; p < 4; p++) {
                    int m = m0 + ty * 8 + 2 * p;
                    *(float2*)&dst[(size_t)n * ND + m] = acc[p][j].f;
                }
            }
        } else if (bid < 144) {
            // w = V @ f (old V)
            int row = (bid - 80) * 8 + (tid >> 5);
            int lane = tid & 31;
            float ssum = 0.f;
            for (int i = lane; i < NS; i += 32) ssum += g_V[row * NS + i] * f[i];
            for (int o = 16; o; o >>= 1) ssum += __shfl_down_sync(~0u, ssum, o);
            if (!lane) g_w[row] = ssum;
        }
        gsync();

        // ---- Phase B: Q partials = FV @ F over 15 needed tiles x 8 chunks ----
        if (bid < 120) {
            const int tile = bid >> 3, chunk = bid & 7;
            const int m0 = c_tM0[tile], n0 = c_tN0[tile];
            const int k0 = chunk * 64;
            UF2 acc[4][8];
            gemm128_core(g_FVp[0] + (size_t)k0 * ND + m0, ND, 4, (size_t)NS * ND,
                         F + (size_t)k0 * ND + n0, ND, 64, smf, acc);
            float* dst = g_QP[tile * 8 + chunk];
            const int tx = tid & 15, ty = tid >> 4;
#pragma unroll
            for (int p = 0; p < 4; p++) {
                int r0 = ty * 8 + 2 * p;
                float4 x0 = make_float4(acc[p][0].f.x, acc[p][1].f.x, acc[p][2].f.x, acc[p][3].f.x);
                float4 x1 = make_float4(acc[p][4].f.x, acc[p][5].f.x, acc[p][6].f.x, acc[p][7].f.x);
                float4 y0 = make_float4(acc[p][0].f.y, acc[p][1].f.y, acc[p][2].f.y, acc[p][3].f.y);
                float4 y1 = make_float4(acc[p][4].f.y, acc[p][5].f.y, acc[p][6].f.y, acc[p][7].f.y);
                *(float4*)&dst[r0 * 128 + tx * 8] = x0;
                *(float4*)&dst[r0 * 128 + tx * 8 + 4] = x1;
                *(float4*)&dst[(r0 + 1) * 128 + tx * 8] = y0;
                *(float4*)&dst[(r0 + 1) * 128 + tx * 8 + 4] = y1;
            }
        } else if (bid < 123) {
            // q = c + FV@f + Ft@v  (coalesced over column a)
            int a = (bid - 120) * 256 + tid;
            if (a < ND) {
                float ssum = c[a];
#pragma unroll 4
                for (int i = 0; i < NS; i++) {
                    float fv = g_FVp[0][(size_t)i * ND + a] + g_FVp[1][(size_t)i * ND + a]
                             + g_FVp[2][(size_t)i * ND + a] + g_FVp[3][(size_t)i * ND + a];
                    ssum += fv * f[i] + F[(size_t)i * ND + a] * g_v[i];
                }
                g_q[a] = ssum;
            }
        }
        gsync();

        // ---- Phase Bc: combine Q = C + sum(QP), mirror upper xx tiles ----
        for (int idx = bid * 256 + tid; idx < 15 * 16384; idx += nb * 256) {
            int tile = idx >> 14, e = idx & 16383;
            int m = e >> 7, n = e & 127;
            int gm = c_tM0[tile] + m, gn = c_tN0[tile] + n;
            float ssum = C[(size_t)gm * ND + gn];
#pragma unroll
            for (int ch = 0; ch < 8; ch++) ssum += g_QP[tile * 8 + ch][e];
            g_Q[(size_t)gm * ND + gn] = ssum;
            if (c_mir[tile]) g_Q[(size_t)gn * ND + gm] = ssum;
        }
        gsync();

        // ---- Phase C0 (s==0): X0 = I / ||Quu||_inf ----
        if (s == 0) {
            if (bid == 0) {
                float m = 0.f;
                if (tid < NC) {
                    float ssum = 0.f;
                    const float* Qr = &g_Q[(size_t)(NS + tid) * ND + NS];
                    for (int j = 0; j < NC; j++) ssum += fabsf(Qr[j]);
                    m = ssum;
                }
                red[tid] = m; __syncthreads();
                for (int st = 128; st; st >>= 1) {
                    if (tid < st) red[tid] = fmaxf(red[tid], red[tid + st]);
                    __syncthreads();
                }
                float inv = 1.f / red[0];
                __syncthreads();
                for (int i = tid; i < NC * NC; i += 256) {
                    int r2 = i >> 7, c2 = i & 127;
                    g_X[0][i] = (r2 == c2) ? inv : 0.f;
                }
            }
            gsync();
        }

        // ---- Phase C: Newton-Schulz (warm-started) ----
        int niter = (s == 0) ? 20 : ((s < 8) ? 4 : 2);
        for (int it = 0; it < niter; it++) {
            if (bid < 32) newton_strip(g_X[cur], g_X[cur ^ 1], sm);
            cur ^= 1;
            gsync();
        }

        // ---- Phase D: K = -X @ Qux (16 tiles 64x64, Kd=128); bid16: k,const ----
        if (bid < 16) {
            const int m0 = (bid >> 3) * 64, n0 = (bid & 7) * 64;
            gemm64_tile(g_X[cur] + m0, NC,
                        g_Q + (size_t)NS * ND + n0, ND,
                        nullptr, 0,
                        g_K + (size_t)m0 * NS + n0,
                        outK + (size_t)t * NC * NS + (size_t)m0 * NS + n0, NS,
                        128, -1.f, smf);
        } else if (bid == 16) {
            float* ksh = sm; float* quk = sm + 132;
            float kv = 0.f;
            if (tid < NC) {
                const float* Xr = g_X[cur] + tid * NC;
                for (int j = 0; j < NC; j++) kv += Xr[j] * g_q[NS + j];
                kv = -kv;
                ksh[tid] = kv; g_k[tid] = kv; outk[(size_t)t * NC + tid] = kv;
            }
            __syncthreads();
            if (tid < NC) {
                float qk = 0.f;
                const float* Qr = &g_Q[(size_t)(NS + tid) * ND + NS];
                for (int j = 0; j < NC; j++) qk = fmaf(Qr[j], ksh[j], qk);
                quk[tid] = qk;
            }
            __syncthreads();
            float pp1 = 0.f, pp2 = 0.f, pp3 = 0.f, pp4 = 0.f;
            for (int i = tid; i < NC; i += 256) { pp1 += ksh[i] * quk[i]; pp2 += ksh[i] * g_q[NS + i]; }
            for (int i = tid; i < NS; i += 256) { pp3 += f[i] * g_w[i];   pp4 += f[i] * g_v[i]; }
            float parts[4] = {pp1, pp2, pp3, pp4};
            float res[4];
            for (int qd = 0; qd < 4; qd++) {
                red[tid] = parts[qd]; __syncthreads();
                for (int st = 128; st; st >>= 1) {
                    if (tid < st) red[tid] += red[tid + st];
                    __syncthreads();
                }
                res[qd] = red[0]; __syncthreads();
            }
            if (tid == 0) {
                float cn = g_cst + 0.5f * res[0] + res[1] + 0.5f * res[2] + res[3];
                g_cst = cn;
                outc[t] = cn;
            }
        }
        gsync();

        // ---- Phase E: Vn = Qxx + K^T @ Qux (64 tiles 64x64, Kd=128); vn ----
        if (bid < 64) {
            const int m0 = (bid >> 3) * 64, n0 = (bid & 7) * 64;
            gemm64_tile(g_K + m0, NS,
                        g_Q + (size_t)NS * ND + n0, ND,
                        g_Q + (size_t)m0 * ND + n0, ND,
                        g_V + (size_t)m0 * NS + n0,
                        outV + (size_t)t * NS * NS + (size_t)m0 * NS + n0, NS,
                        128, 1.f, smf);
        } else if (bid < 66) {
            // vn = qx + Qxu @ k = qx + Qux^T @ k  (coalesced over x)
            int x = (bid - 64) * 256 + tid;
            float ssum = 0.f;
#pragma unroll 4
            for (int j = 0; j < NC; j++)
                ssum += g_Q[(size_t)(NS + j) * ND + x] * g_k[j];
            float val = g_q[x] + ssum;
            g_v[x] = val;
            outv[(size_t)t * NS + x] = val;
        }
        gsync();
    }
}

// ---------------- host -------------------------------------------------------------
extern "C" void kernel_launch(void* const* d_in, const int* in_sizes, int n_in,
                              void* d_out, int out_size) {
    (void)in_sizes; (void)n_in; (void)out_size;
    const float* F = (const float*)d_in[0];
    const float* f = (const float*)d_in[1];
    const float* C = (const float*)d_in[2];
    const float* c = (const float*)d_in[3];
    cudaFuncSetAttribute(lqr_kernel, cudaFuncAttributeMaxDynamicSharedMemorySize, DSMEM);
    lqr_kernel<<<NBLK, 256, DSMEM>>>(F, f, C, c, (float*)d_out);
}

// round 11
// speedup vs baseline: 1.0021x; 1.0021x over previous
#include <cuda_runtime.h>
#include <cstdint>

#define NS 512
#define NC 128
#define ND 640
#define TT 256
#define NBLK 148
#define DSMEM (2 * 128 * 68 * 4)   // 69632 bytes: two 128x68 fp32 slabs

// ---------------- persistent device state (no allocation allowed) ----------------
__device__ __align__(16) float g_V[NS * NS];     // carry V (512x512), symmetric
__device__ __align__(16) float g_FVt[NS * ND];   // FVt[k][m] = FV[m][k] (512x640)
__device__ __align__(16) float g_Q[ND * ND];     // Q (640x640), symmetric
__device__ __align__(16) float g_K[NC * NS];     // K (128x512)
__device__ __align__(16) float g_X[2][NC * NC];  // Newton ping-pong, symmetric
__device__ float g_q[ND], g_w[NS], g_v[NS], g_k[NC], g_cst;
__device__ unsigned g_arrive;
__device__ volatile unsigned g_gen;

// ---------------- grid-wide barrier ----------------------------------------------
__device__ __forceinline__ void gsync() {
    __syncthreads();
    if (threadIdx.x == 0) {
        unsigned gen = g_gen;
        __threadfence();
        if (atomicAdd(&g_arrive, 1u) == gridDim.x - 1) {
            g_arrive = 0;
            __threadfence();
            g_gen = gen + 1;
        } else {
            while (g_gen == gen) { __nanosleep(64); }
        }
        __threadfence();
    }
    __syncthreads();
}

// ---------------- packed f32x2 helpers --------------------------------------------
union UF2 { unsigned long long u; float2 f; };
__device__ __forceinline__ void ffma2(unsigned long long& d,
                                      unsigned long long a, unsigned long long b) {
    asm("fma.rn.f32x2 %0, %1, %2, %0;" : "+l"(d) : "l"(a), "l"(b));
}
__device__ __forceinline__ unsigned long long dup2(float x) {
    unsigned long long r; unsigned xi = __float_as_uint(x);
    asm("mov.b64 %0, {%1, %1};" : "=l"(r) : "r"(xi));
    return r;
}

// ---------------- K-blocked 64x64 tile GEMM (proven R10 inner pattern) ------------
// D = alpha * (sum_k A[k][m-win] * B[k][n-win]) + Cin.  A/B natural [k][col] layout,
// pre-offset to the tile's column window. K processed in chunks of 128 rows.
__device__ __forceinline__ void gemmKB(
    const float* __restrict__ Asrc, int lda,
    const float* __restrict__ Bsrc, int ldb,
    const float* __restrict__ Cin, int ldc,
    float* __restrict__ D1, float* __restrict__ D2, int ldd,
    int KC, float alpha, float* sm)
{
    float* As = sm;
    float* Bs = sm + 128 * 68;
    const int tid = threadIdx.x;
    const int tx = tid & 15, ty = tid >> 4;
    UF2 acc[2][4];
#pragma unroll
    for (int p = 0; p < 2; p++)
#pragma unroll
        for (int j = 0; j < 4; j++) acc[p][j].u = 0ull;

    for (int k0 = 0; k0 < KC; k0 += 128) {
        __syncthreads();   // previous chunk's readers done before re-staging
        for (int u = tid; u < 128 * 16; u += 256) {
            int kk = u >> 4, c4 = (u & 15) << 2;
            *(float4*)&As[kk * 68 + c4] =
                *(const float4*)(Asrc + (size_t)(k0 + kk) * lda + c4);
            *(float4*)&Bs[kk * 68 + c4] =
                *(const float4*)(Bsrc + (size_t)(k0 + kk) * ldb + c4);
        }
        __syncthreads();
#pragma unroll 4
        for (int kk = 0; kk < 128; kk++) {
            ulonglong2 ap = *(const ulonglong2*)&As[kk * 68 + ty * 4];
            float4 b = *(const float4*)&Bs[kk * 68 + tx * 4];
            unsigned long long bd0 = dup2(b.x), bd1 = dup2(b.y);
            unsigned long long bd2 = dup2(b.z), bd3 = dup2(b.w);
            ffma2(acc[0][0].u, ap.x, bd0); ffma2(acc[0][1].u, ap.x, bd1);
            ffma2(acc[0][2].u, ap.x, bd2); ffma2(acc[0][3].u, ap.x, bd3);
            ffma2(acc[1][0].u, ap.y, bd0); ffma2(acc[1][1].u, ap.y, bd1);
            ffma2(acc[1][2].u, ap.y, bd2); ffma2(acc[1][3].u, ap.y, bd3);
        }
    }
    __syncthreads();
#pragma unroll
    for (int p = 0; p < 2; p++) {
        int r = ty * 4 + 2 * p;
        float ox[4], oy[4];
#pragma unroll
        for (int j = 0; j < 4; j++) {
            ox[j] = alpha * acc[p][j].f.x;
            oy[j] = alpha * acc[p][j].f.y;
            if (Cin) {
                ox[j] += Cin[(size_t)r * ldc + tx * 4 + j];
                oy[j] += Cin[(size_t)(r + 1) * ldc + tx * 4 + j];
            }
        }
        float4 vx = make_float4(ox[0], ox[1], ox[2], ox[3]);
        float4 vy = make_float4(oy[0], oy[1], oy[2], oy[3]);
        *(float4*)&D1[(size_t)r * ldd + tx * 4] = vx;
        *(float4*)&D1[(size_t)(r + 1) * ldd + tx * 4] = vy;
        if (D2) {
            *(float4*)&D2[(size_t)r * ldd + tx * 4] = vx;
            *(float4*)&D2[(size_t)(r + 1) * ldd + tx * 4] = vy;
        }
    }
}

// ---------------- Newton-Schulz strip (proven R6/R10) -----------------------------
__device__ __forceinline__ void newton_strip(const float* __restrict__ Xin,
                                             float* __restrict__ Xout, float* sm)
{
    float* Qs = sm;           // [128][20]
    float* Xs = sm + 2560;    // [128][4]
    float* Ts = sm + 3072;    // [128][4]
    const int tid = threadIdx.x;
    const int J = blockIdx.x * 4;
    for (int i = tid; i < 512; i += 256) {
        int r = i >> 2, jj = i & 3;
        Xs[i] = Xin[r * NC + J + jj];
    }
    __syncthreads();
    const int r = tid >> 1, jh = (tid & 1) * 2;
    float t0 = 0.f, t1 = 0.f;
    for (int k0 = 0; k0 < NC; k0 += 16) {
        for (int i = tid; i < 512; i += 256) {
            int rr = i >> 2, q4 = i & 3;
            *(float4*)&Qs[rr * 20 + q4 * 4] =
                *(const float4*)&g_Q[(size_t)(NS + rr) * ND + NS + k0 + q4 * 4];
        }
        __syncthreads();
#pragma unroll
        for (int kk = 0; kk < 16; kk++) {
            float a = Qs[r * 20 + kk];
            t0 = fmaf(a, Xs[(k0 + kk) * 4 + jh], t0);
            t1 = fmaf(a, Xs[(k0 + kk) * 4 + jh + 1], t1);
        }
        __syncthreads();
    }
    Ts[r * 4 + jh] = t0; Ts[r * 4 + jh + 1] = t1;
    __syncthreads();
    float x0 = 0.f, x1 = 0.f;
    for (int k0 = 0; k0 < NC; k0 += 16) {
        for (int i = tid; i < 512; i += 256) {
            int rr = i >> 2, q4 = i & 3;
            *(float4*)&Qs[rr * 20 + q4 * 4] =
                *(const float4*)&Xin[rr * NC + k0 + q4 * 4];
        }
        __syncthreads();
#pragma unroll
        for (int kk = 0; kk < 16; kk++) {
            float a = Qs[r * 20 + kk];
            x0 = fmaf(a, Ts[(k0 + kk) * 4 + jh], x0);
            x1 = fmaf(a, Ts[(k0 + kk) * 4 + jh + 1], x1);
        }
        __syncthreads();
    }
    Xout[r * NC + J + jh]     = 2.f * Xs[r * 4 + jh]     - x0;
    Xout[r * NC + J + jh + 1] = 2.f * Xs[r * 4 + jh + 1] - x1;
}

// ---------------- the persistent kernel -------------------------------------------
__global__ void __launch_bounds__(256, 1) lqr_kernel(
    const float* __restrict__ F, const float* __restrict__ f,
    const float* __restrict__ C, const float* __restrict__ c,
    float* __restrict__ out)
{
    extern __shared__ __align__(16) float smf[];
    __shared__ __align__(16) float sm[3600];
    __shared__ float red[264];
    const int bid = blockIdx.x, tid = threadIdx.x, nb = gridDim.x;
    float* outK = out;
    float* outk = outK + (size_t)TT * NC * NS;
    float* outV = outk + (size_t)TT * NC;
    float* outv = outV + (size_t)TT * NS * NS;
    float* outc = outv + (size_t)TT * NS;

    // ---- init: V = C[:n,:n], v = c[:n], const = 0 ----
    for (int i = bid * 256 + tid; i < NS * NS; i += nb * 256) {
        int r = i >> 9, cq = i & (NS - 1);
        g_V[i] = C[(size_t)r * ND + cq];
    }
    if (bid == nb - 1) {
        for (int i = tid; i < NS; i += 256) g_v[i] = c[i];
        if (tid == 0) g_cst = 0.f;
    }
    gsync();

    int cur = 0;
    for (int s = 0; s < TT; s++) {
        const int t = TT - 1 - s;

        // ---- Phase A: FVt = V @ F (80 tiles 64x64, K=512); w = V @ f ----
        // FVt[n][m] = sum_k V[k][n] * F[k][m]  (V symmetric => = FV[m][n])
        if (bid < 80) {
            const int n0 = (bid / 10) * 64, m0 = (bid % 10) * 64;
            gemmKB(g_V + n0, NS, F + m0, ND, nullptr, 0,
                   g_FVt + (size_t)n0 * ND + m0, nullptr, ND,
                   NS, 1.f, smf);
        } else {
            int row = (bid - 80) * 8 + (tid >> 5);
            int lane = tid & 31;
            if (row < NS) {
                float ssum = 0.f;
                for (int i = lane; i < NS; i += 32) ssum += g_V[row * NS + i] * f[i];
                for (int o = 16; o; o >>= 1) ssum += __shfl_down_sync(~0u, ssum, o);
                if (!lane) g_w[row] = ssum;
            }
        }
        gsync();

        // ---- Phase B: Q = C + FV @ F (100 tiles 64x64, K=512); q vector ----
        // Q[m][n] = C[m][n] + sum_k FVt[k][m] * F[k][n]
        if (bid < 100) {
            const int m0 = (bid / 10) * 64, n0 = (bid % 10) * 64;
            gemmKB(g_FVt + m0, ND, F + n0, ND,
                   C + (size_t)m0 * ND + n0, ND,
                   g_Q + (size_t)m0 * ND + n0, nullptr, ND,
                   NS, 1.f, smf);
        } else if (bid < 103) {
            // q = c + FV@f + Ft@v   (coalesced over column a)
            int a = (bid - 100) * 256 + tid;
            if (a < ND) {
                float ssum = c[a];
#pragma unroll 4
                for (int i = 0; i < NS; i++)
                    ssum += g_FVt[(size_t)i * ND + a] * f[i]
                          + F[(size_t)i * ND + a] * g_v[i];
                g_q[a] = ssum;
            }
        }
        gsync();

        // ---- Phase C0 (s==0): X0 = I / ||Quu||_inf ----
        if (s == 0) {
            if (bid == 0) {
                float m = 0.f;
                if (tid < NC) {
                    float ssum = 0.f;
                    const float* Qr = &g_Q[(size_t)(NS + tid) * ND + NS];
                    for (int j = 0; j < NC; j++) ssum += fabsf(Qr[j]);
                    m = ssum;
                }
                red[tid] = m; __syncthreads();
                for (int st = 128; st; st >>= 1) {
                    if (tid < st) red[tid] = fmaxf(red[tid], red[tid + st]);
                    __syncthreads();
                }
                float inv = 1.f / red[0];
                __syncthreads();
                for (int i = tid; i < NC * NC; i += 256) {
                    int r2 = i >> 7, c2 = i & 127;
                    g_X[0][i] = (r2 == c2) ? inv : 0.f;
                }
            }
            gsync();
        }

        // ---- Phase C: Newton-Schulz (warm-started) ----
        int niter = (s == 0) ? 20 : ((s < 8) ? 4 : 2);
        for (int it = 0; it < niter; it++) {
            if (bid < 32) newton_strip(g_X[cur], g_X[cur ^ 1], sm);
            cur ^= 1;
            gsync();
        }

        // ---- Phase D: K = -X @ Qux (16 tiles 64x64, K=128); bid16: k, const ----
        // K[m][n] = -sum_k X[k][m] * Qux[k][n]   (X symmetric)
        if (bid < 16) {
            const int m0 = (bid >> 3) * 64, n0 = (bid & 7) * 64;
            gemmKB(g_X[cur] + m0, NC,
                   g_Q + (size_t)NS * ND + n0, ND,
                   nullptr, 0,
                   g_K + (size_t)m0 * NS + n0,
                   outK + (size_t)t * NC * NS + (size_t)m0 * NS + n0, NS,
                   NC, -1.f, smf);
        } else if (bid == 16) {
            float* ksh = sm; float* quk = sm + 132;
            float kv = 0.f;
            if (tid < NC) {
                const float* Xr = g_X[cur] + tid * NC;
                for (int j = 0; j < NC; j++) kv += Xr[j] * g_q[NS + j];
                kv = -kv;
                ksh[tid] = kv; g_k[tid] = kv; outk[(size_t)t * NC + tid] = kv;
            }
            __syncthreads();
            if (tid < NC) {
                float qk = 0.f;
                const float* Qr = &g_Q[(size_t)(NS + tid) * ND + NS];
                for (int j = 0; j < NC; j++) qk = fmaf(Qr[j], ksh[j], qk);
                quk[tid] = qk;
            }
            __syncthreads();
            float pp1 = 0.f, pp2 = 0.f, pp3 = 0.f, pp4 = 0.f;
            for (int i = tid; i < NC; i += 256) { pp1 += ksh[i] * quk[i]; pp2 += ksh[i] * g_q[NS + i]; }
            for (int i = tid; i < NS; i += 256) { pp3 += f[i] * g_w[i];   pp4 += f[i] * g_v[i]; }
            float parts[4] = {pp1, pp2, pp3, pp4};
            float res[4];
            for (int qd = 0; qd < 4; qd++) {
                red[tid] = parts[qd]; __syncthreads();
                for (int st = 128; st; st >>= 1) {
                    if (tid < st) red[tid] += red[tid + st];
                    __syncthreads();
                }
                res[qd] = red[0]; __syncthreads();
            }
            if (tid == 0) {
                float cn = g_cst + 0.5f * res[0] + res[1] + 0.5f * res[2] + res[3];
                g_cst = cn;
                outc[t] = cn;
            }
        }
        gsync();

        // ---- Phase E: Vn = Qxx + Qxu @ K (64 tiles 64x64, K=128); vn vector ----
        // Vn[m][n] = Qxx[m][n] + sum_k Qux[k][m] * K[k][n]   (Q symmetric)
        if (bid < 64) {
            const int m0 = (bid >> 3) * 64, n0 = (bid & 7) * 64;
            gemmKB(g_Q + (size_t)NS * ND + m0, ND,
                   g_K + n0, NS,
                   g_Q + (size_t)m0 * ND + n0, ND,
                   g_V + (size_t)m0 * NS + n0,
                   outV + (size_t)t * NS * NS + (size_t)m0 * NS + n0, NS,
                   NC, 1.f, smf);
        } else if (bid < 66) {
            // vn = qx + Qxu @ k = qx + Qux^T @ k  (coalesced over x)
            int x = (bid - 64) * 256 + tid;
            float ssum = 0.f;
#pragma unroll 4
            for (int j = 0; j < NC; j++)
                ssum += g_Q[(size_t)(NS + j) * ND + x] * g_k[j];
            float val = g_q[x] + ssum;
            g_v[x] = val;
            outv[(size_t)t * NS + x] = val;
        }
        gsync();
    }
}

// ---------------- host -------------------------------------------------------------
extern "C" void kernel_launch(void* const* d_in, const int* in_sizes, int n_in,
                              void* d_out, int out_size) {
    (void)in_sizes; (void)n_in; (void)out_size;
    const float* F = (const float*)d_in[0];
    const float* f = (const float*)d_in[1];
    const float* C = (const float*)d_in[2];
    const float* c = (const float*)d_in[3];
    cudaFuncSetAttribute(lqr_kernel, cudaFuncAttributeMaxDynamicSharedMemorySize, DSMEM);
    lqr_kernel<<<NBLK, 256, DSMEM>>>(F, f, C, c, (float*)d_out);
}

// round 13
// speedup vs baseline: 1.4105x; 1.4075x over previous
#include <cuda_runtime.h>
#include <cstdint>

#define NS 512
#define NC 128
#define ND 640
#define TT 256
#define NBLK 148

// ---------------- persistent device state (no allocation allowed) ----------------
__device__ __align__(16) float g_V[NS * NS];     // carry V (512x512), symmetric
__device__ __align__(16) float g_FVt[NS * ND];   // FVt[k][m] = FV[m][k] (512x640)
__device__ __align__(16) float g_Q[ND * ND];     // Q (640x640), symmetric
__device__ __align__(16) float g_K[NC * NS];     // K (128x512)
__device__ __align__(16) float g_X[2][NC * NC];  // Newton ping-pong, symmetric
__device__ float g_q[ND], g_w[NS], g_v[NS], g_k[NC], g_cst;
__device__ unsigned g_arrive;
__device__ volatile unsigned g_gen;

// ---------------- grid-wide barrier ----------------------------------------------
__device__ __forceinline__ void gsync() {
    __syncthreads();
    if (threadIdx.x == 0) {
        unsigned gen = g_gen;
        __threadfence();
        if (atomicAdd(&g_arrive, 1u) == gridDim.x - 1) {
            g_arrive = 0;
            __threadfence();
            g_gen = gen + 1;
        } else {
            while (g_gen == gen) { __nanosleep(64); }
        }
        __threadfence();
    }
    __syncthreads();
}

// ---------------- packed f32x2 helpers --------------------------------------------
union UF2 { unsigned long long u; float2 f; };
__device__ __forceinline__ void ffma2(unsigned long long& d,
                                      unsigned long long a, unsigned long long b) {
    asm("fma.rn.f32x2 %0, %1, %2, %0;" : "+l"(d) : "l"(a), "l"(b));
}
__device__ __forceinline__ unsigned long long dup2(float x) {
    unsigned long long r; unsigned xi = __float_as_uint(x);
    asm("mov.b64 %0, {%1, %1};" : "=l"(r) : "r"(xi));
    return r;
}

// ---------------- 64x64 tile GEMM, 16-row slabs + register prefetch ---------------
// D = alpha * (sum_k A[k][m-win] * B[k][n-win]) + Cin.  A/B natural [k][col] layout,
// pre-offset to the tile's column window. R6-proven staging + R11-proven compute.
__device__ __forceinline__ void gemmKB(
    const float* __restrict__ Asrc, int lda,
    const float* __restrict__ Bsrc, int ldb,
    const float* __restrict__ Cin, int ldc,
    float* __restrict__ D1, float* __restrict__ D2, int ldd,
    int KC, float alpha, float* sm)
{
    float* As = sm;            // [16][68]
    float* Bs = sm + 16 * 68;  // [16][68]
    const int tid = threadIdx.x;
    const int tx = tid & 15, ty = tid >> 4;
    const int sr = tid >> 4, sc = (tid & 15) << 2;   // staging row / col
    const float* Ap = Asrc + (size_t)sr * lda + sc;
    const float* Bp = Bsrc + (size_t)sr * ldb + sc;
    UF2 acc[2][4];
#pragma unroll
    for (int p = 0; p < 2; p++)
#pragma unroll
        for (int j = 0; j < 4; j++) acc[p][j].u = 0ull;

    float4 av = *(const float4*)Ap;
    float4 bv = *(const float4*)Bp;
    for (int k0 = 0; k0 < KC; k0 += 16) {
        *(float4*)&As[sr * 68 + sc] = av;
        *(float4*)&Bs[sr * 68 + sc] = bv;
        __syncthreads();
        if (k0 + 16 < KC) {   // register prefetch of the next slab (hides latency)
            av = *(const float4*)(Ap + (size_t)(k0 + 16) * lda);
            bv = *(const float4*)(Bp + (size_t)(k0 + 16) * ldb);
        }
#pragma unroll
        for (int kk = 0; kk < 16; kk++) {
            ulonglong2 ap = *(const ulonglong2*)&As[kk * 68 + ty * 4];
            float4 b = *(const float4*)&Bs[kk * 68 + tx * 4];
            unsigned long long bd0 = dup2(b.x), bd1 = dup2(b.y);
            unsigned long long bd2 = dup2(b.z), bd3 = dup2(b.w);
            ffma2(acc[0][0].u, ap.x, bd0); ffma2(acc[0][1].u, ap.x, bd1);
            ffma2(acc[0][2].u, ap.x, bd2); ffma2(acc[0][3].u, ap.x, bd3);
            ffma2(acc[1][0].u, ap.y, bd0); ffma2(acc[1][1].u, ap.y, bd1);
            ffma2(acc[1][2].u, ap.y, bd2); ffma2(acc[1][3].u, ap.y, bd3);
        }
        __syncthreads();
    }
#pragma unroll
    for (int p = 0; p < 2; p++) {
        int r = ty * 4 + 2 * p;
        float ox[4], oy[4];
#pragma unroll
        for (int j = 0; j < 4; j++) {
            ox[j] = alpha * acc[p][j].f.x;
            oy[j] = alpha * acc[p][j].f.y;
            if (Cin) {
                ox[j] += Cin[(size_t)r * ldc + tx * 4 + j];
                oy[j] += Cin[(size_t)(r + 1) * ldc + tx * 4 + j];
            }
        }
        float4 vx = make_float4(ox[0], ox[1], ox[2], ox[3]);
        float4 vy = make_float4(oy[0], oy[1], oy[2], oy[3]);
        *(float4*)&D1[(size_t)r * ldd + tx * 4] = vx;
        *(float4*)&D1[(size_t)(r + 1) * ldd + tx * 4] = vy;
        if (D2) {
            *(float4*)&D2[(size_t)r * ldd + tx * 4] = vx;
            *(float4*)&D2[(size_t)(r + 1) * ldd + tx * 4] = vy;
        }
    }
}

// ---------------- Newton-Schulz strip (proven R6/R10/R11) -------------------------
__device__ __forceinline__ void newton_strip(const float* __restrict__ Xin,
                                             float* __restrict__ Xout, float* sm)
{
    float* Qs = sm;           // [128][20]
    float* Xs = sm + 2560;    // [128][4]
    float* Ts = sm + 3072;    // [128][4]
    const int tid = threadIdx.x;
    const int J = blockIdx.x * 4;
    for (int i = tid; i < 512; i += 256) {
        int r = i >> 2, jj = i & 3;
        Xs[i] = Xin[r * NC + J + jj];
    }
    __syncthreads();
    const int r = tid >> 1, jh = (tid & 1) * 2;
    float t0 = 0.f, t1 = 0.f;
    for (int k0 = 0; k0 < NC; k0 += 16) {
        for (int i = tid; i < 512; i += 256) {
            int rr = i >> 2, q4 = i & 3;
            *(float4*)&Qs[rr * 20 + q4 * 4] =
                *(const float4*)&g_Q[(size_t)(NS + rr) * ND + NS + k0 + q4 * 4];
        }
        __syncthreads();
#pragma unroll
        for (int kk = 0; kk < 16; kk++) {
            float a = Qs[r * 20 + kk];
            t0 = fmaf(a, Xs[(k0 + kk) * 4 + jh], t0);
            t1 = fmaf(a, Xs[(k0 + kk) * 4 + jh + 1], t1);
        }
        __syncthreads();
    }
    Ts[r * 4 + jh] = t0; Ts[r * 4 + jh + 1] = t1;
    __syncthreads();
    float x0 = 0.f, x1 = 0.f;
    for (int k0 = 0; k0 < NC; k0 += 16) {
        for (int i = tid; i < 512; i += 256) {
            int rr = i >> 2, q4 = i & 3;
            *(float4*)&Qs[rr * 20 + q4 * 4] =
                *(const float4*)&Xin[rr * NC + k0 + q4 * 4];
        }
        __syncthreads();
#pragma unroll
        for (int kk = 0; kk < 16; kk++) {
            float a = Qs[r * 20 + kk];
            x0 = fmaf(a, Ts[(k0 + kk) * 4 + jh], x0);
            x1 = fmaf(a, Ts[(k0 + kk) * 4 + jh + 1], x1);
        }
        __syncthreads();
    }
    Xout[r * NC + J + jh]     = 2.f * Xs[r * 4 + jh]     - x0;
    Xout[r * NC + J + jh + 1] = 2.f * Xs[r * 4 + jh + 1] - x1;
}

// ---------------- the persistent kernel -------------------------------------------
__global__ void __launch_bounds__(256, 1) lqr_kernel(
    const float* __restrict__ F, const float* __restrict__ f,
    const float* __restrict__ C, const float* __restrict__ c,
    float* __restrict__ out)
{
    __shared__ __align__(16) float sm[3600];
    __shared__ float red[264];
    const int bid = blockIdx.x, tid = threadIdx.x, nb = gridDim.x;
    float* outK = out;
    float* outk = outK + (size_t)TT * NC * NS;
    float* outV = outk + (size_t)TT * NC;
    float* outv = outV + (size_t)TT * NS * NS;
    float* outc = outv + (size_t)TT * NS;

    // ---- init: V = C[:n,:n], v = c[:n], const = 0 ----
    for (int i = bid * 256 + tid; i < NS * NS; i += nb * 256) {
        int r = i >> 9, cq = i & (NS - 1);
        g_V[i] = C[(size_t)r * ND + cq];
    }
    if (bid == nb - 1) {
        for (int i = tid; i < NS; i += 256) g_v[i] = c[i];
        if (tid == 0) g_cst = 0.f;
    }
    gsync();

    int cur = 0;
    for (int s = 0; s < TT; s++) {
        const int t = TT - 1 - s;

        // ---- Phase A: FVt = V @ F (80 tiles 64x64, K=512); w = V @ f ----
        // FVt[n][m] = sum_k V[k][n] * F[k][m]  (V symmetric => = FV[m][n])
        if (bid < 80) {
            const int n0 = (bid / 10) * 64, m0 = (bid % 10) * 64;
            gemmKB(g_V + n0, NS, F + m0, ND, nullptr, 0,
                   g_FVt + (size_t)n0 * ND + m0, nullptr, ND,
                   NS, 1.f, sm);
        } else {
            int row = (bid - 80) * 8 + (tid >> 5);
            int lane = tid & 31;
            if (row < NS) {
                float ssum = 0.f;
                for (int i = lane; i < NS; i += 32) ssum += g_V[row * NS + i] * f[i];
                for (int o = 16; o; o >>= 1) ssum += __shfl_down_sync(~0u, ssum, o);
                if (!lane) g_w[row] = ssum;
            }
        }
        gsync();

        // ---- Phase B: Q = C + FV @ F (100 tiles 64x64, K=512); q vector ----
        // Q[m][n] = C[m][n] + sum_k FVt[k][m] * F[k][n]
        if (bid < 100) {
            const int m0 = (bid / 10) * 64, n0 = (bid % 10) * 64;
            gemmKB(g_FVt + m0, ND, F + n0, ND,
                   C + (size_t)m0 * ND + n0, ND,
                   g_Q + (size_t)m0 * ND + n0, nullptr, ND,
                   NS, 1.f, sm);
        } else if (bid < 103) {
            // q = c + FV@f + Ft@v   (coalesced over column a)
            int a = (bid - 100) * 256 + tid;
            if (a < ND) {
                float ssum = c[a];
#pragma unroll 4
                for (int i = 0; i < NS; i++)
                    ssum += g_FVt[(size_t)i * ND + a] * f[i]
                          + F[(size_t)i * ND + a] * g_v[i];
                g_q[a] = ssum;
            }
        }
        gsync();

        // ---- Phase C0 (s==0): X0 = I / ||Quu||_inf ----
        if (s == 0) {
            if (bid == 0) {
                float m = 0.f;
                if (tid < NC) {
                    float ssum = 0.f;
                    const float* Qr = &g_Q[(size_t)(NS + tid) * ND + NS];
                    for (int j = 0; j < NC; j++) ssum += fabsf(Qr[j]);
                    m = ssum;
                }
                red[tid] = m; __syncthreads();
                for (int st = 128; st; st >>= 1) {
                    if (tid < st) red[tid] = fmaxf(red[tid], red[tid + st]);
                    __syncthreads();
                }
                float inv = 1.f / red[0];
                __syncthreads();
                for (int i = tid; i < NC * NC; i += 256) {
                    int r2 = i >> 7, c2 = i & 127;
                    g_X[0][i] = (r2 == c2) ? inv : 0.f;
                }
            }
            gsync();
        }

        // ---- Phase C: Newton-Schulz (warm-started) ----
        int niter = (s == 0) ? 20 : ((s < 8) ? 4 : 2);
        for (int it = 0; it < niter; it++) {
            if (bid < 32) newton_strip(g_X[cur], g_X[cur ^ 1], sm);
            cur ^= 1;
            gsync();
        }

        // ---- Phase D: K = -X @ Qux (16 tiles 64x64, K=128); bid16: k, const ----
        // K[m][n] = -sum_k X[k][m] * Qux[k][n]   (X symmetric)
        if (bid < 16) {
            const int m0 = (bid >> 3) * 64, n0 = (bid & 7) * 64;
            gemmKB(g_X[cur] + m0, NC,
                   g_Q + (size_t)NS * ND + n0, ND,
                   nullptr, 0,
                   g_K + (size_t)m0 * NS + n0,
                   outK + (size_t)t * NC * NS + (size_t)m0 * NS + n0, NS,
                   NC, -1.f, sm);
        } else if (bid == 16) {
            float* ksh = sm; float* quk = sm + 132;
            float kv = 0.f;
            if (tid < NC) {
                const float* Xr = g_X[cur] + tid * NC;
                for (int j = 0; j < NC; j++) kv += Xr[j] * g_q[NS + j];
                kv = -kv;
                ksh[tid] = kv; g_k[tid] = kv; outk[(size_t)t * NC + tid] = kv;
            }
            __syncthreads();
            if (tid < NC) {
                float qk = 0.f;
                const float* Qr = &g_Q[(size_t)(NS + tid) * ND + NS];
                for (int j = 0; j < NC; j++) qk = fmaf(Qr[j], ksh[j], qk);
                quk[tid] = qk;
            }
            __syncthreads();
            float pp1 = 0.f, pp2 = 0.f, pp3 = 0.f, pp4 = 0.f;
            for (int i = tid; i < NC; i += 256) { pp1 += ksh[i] * quk[i]; pp2 += ksh[i] * g_q[NS + i]; }
            for (int i = tid; i < NS; i += 256) { pp3 += f[i] * g_w[i];   pp4 += f[i] * g_v[i]; }
            float parts[4] = {pp1, pp2, pp3, pp4};
            float res[4];
            for (int qd = 0; qd < 4; qd++) {
                red[tid] = parts[qd]; __syncthreads();
                for (int st = 128; st; st >>= 1) {
                    if (tid < st) red[tid] += red[tid + st];
                    __syncthreads();
                }
                res[qd] = red[0]; __syncthreads();
            }
            if (tid == 0) {
                float cn = g_cst + 0.5f * res[0] + res[1] + 0.5f * res[2] + res[3];
                g_cst = cn;
                outc[t] = cn;
            }
        }
        gsync();

        // ---- Phase E: Vn = Qxx + Qxu @ K (64 tiles 64x64, K=128); vn vector ----
        // Vn[m][n] = Qxx[m][n] + sum_k Qux[k][m] * K[k][n]   (Q symmetric)
        if (bid < 64) {
            const int m0 = (bid >> 3) * 64, n0 = (bid & 7) * 64;
            gemmKB(g_Q + (size_t)NS * ND + m0, ND,
                   g_K + n0, NS,
                   g_Q + (size_t)m0 * ND + n0, ND,
                   g_V + (size_t)m0 * NS + n0,
                   outV + (size_t)t * NS * NS + (size_t)m0 * NS + n0, NS,
                   NC, 1.f, sm);
        } else if (bid < 66) {
            // vn = qx + Qxu @ k = qx + Qux^T @ k  (coalesced over x)
            int x = (bid - 64) * 256 + tid;
            float ssum = 0.f;
#pragma unroll 4
            for (int j = 0; j < NC; j++)
                ssum += g_Q[(size_t)(NS + j) * ND + x] * g_k[j];
            float val = g_q[x] + ssum;
            g_v[x] = val;
            outv[(size_t)t * NS + x] = val;
        }
        gsync();
    }
}

// ---------------- host -------------------------------------------------------------
extern "C" void kernel_launch(void* const* d_in, const int* in_sizes, int n_in,
                              void* d_out, int out_size) {
    (void)in_sizes; (void)n_in; (void)out_size;
    const float* F = (const float*)d_in[0];
    const float* f = (const float*)d_in[1];
    const float* C = (const float*)d_in[2];
    const float* c = (const float*)d_in[3];
    lqr_kernel<<<NBLK, 256>>>(F, f, C, c, (float*)d_out);
}

// round 14
// speedup vs baseline: 1.7141x; 1.2153x over previous
#include <cuda_runtime.h>
#include <cstdint>

#define NS 512
#define NC 128
#define ND 640
#define TT 256
#define NBLK 148

// ---------------- persistent device state (no allocation allowed) ----------------
__device__ __align__(16) float g_V[NS * NS];     // carry V (512x512), symmetric
__device__ __align__(16) float g_FVt[NS * ND];   // FVt[k][m] = FV[m][k] (512x640)
__device__ __align__(16) float g_Q[ND * ND];     // Q (640x640), symmetric
__device__ __align__(16) float g_K[NC * NS];     // K (128x512)
__device__ __align__(16) float g_X[2][NC * NC];  // Newton ping-pong, ~symmetric
__device__ float g_q[ND], g_w[NS], g_v[NS], g_k[NC], g_cst;
__device__ unsigned g_arrive;
__device__ volatile unsigned g_gen;

// ---------------- grid-wide barrier ----------------------------------------------
__device__ __forceinline__ void gsync() {
    __syncthreads();
    if (threadIdx.x == 0) {
        unsigned gen = g_gen;
        __threadfence();
        if (atomicAdd(&g_arrive, 1u) == gridDim.x - 1) {
            g_arrive = 0;
            __threadfence();
            g_gen = gen + 1;
        } else {
            while (g_gen == gen) { __nanosleep(64); }
        }
        __threadfence();
    }
    __syncthreads();
}

// ---------------- packed f32x2 helpers --------------------------------------------
union UF2 { unsigned long long u; float2 f; };
__device__ __forceinline__ void ffma2(unsigned long long& d,
                                      unsigned long long a, unsigned long long b) {
    asm("fma.rn.f32x2 %0, %1, %2, %0;" : "+l"(d) : "l"(a), "l"(b));
}

// ---------------- 64x64 tile GEMM: dup-A staging, zero inner-loop MOVs ------------
// D = alpha * (sum_k A[k][m-win] * B[k][n-win]) + Cin.  A/B natural [k][col] layout,
// pre-offset to the tile's column window. A staged DUPLICATED pairwise in smem so
// both f32x2 operand packs come straight from LDS (R6-proven layout, R13 phases).
__device__ __forceinline__ void gemmKB(
    const float* __restrict__ Asrc, int lda,
    const float* __restrict__ Bsrc, int ldb,
    const float* __restrict__ Cin, int ldc,
    float* __restrict__ D1, float* __restrict__ D2, int ldd,
    int KC, float alpha, float* sm)
{
    float* AsD = sm;             // [16][136] dup'd (row = 544B, 16B-aligned)
    float* Bs  = sm + 16 * 136;  // [16][68]
    const int tid = threadIdx.x;
    const int tx = tid & 15, ty = tid >> 4;
    const int sr = tid >> 4, sc = (tid & 15) << 2;   // staging row / col
    const float* Ap = Asrc + (size_t)sr * lda + sc;
    const float* Bp = Bsrc + (size_t)sr * ldb + sc;
    UF2 acc[4][2];
#pragma unroll
    for (int p = 0; p < 4; p++) { acc[p][0].u = 0ull; acc[p][1].u = 0ull; }

    float4 av = *(const float4*)Ap;
    float4 bv = *(const float4*)Bp;
    for (int k0 = 0; k0 < KC; k0 += 16) {
        float4 d0 = make_float4(av.x, av.x, av.y, av.y);
        float4 d1 = make_float4(av.z, av.z, av.w, av.w);
        *(float4*)&AsD[sr * 136 + 2 * sc]     = d0;
        *(float4*)&AsD[sr * 136 + 2 * sc + 4] = d1;
        *(float4*)&Bs[sr * 68 + sc] = bv;
        __syncthreads();
        if (k0 + 16 < KC) {   // register prefetch of next slab
            av = *(const float4*)(Ap + (size_t)(k0 + 16) * lda);
            bv = *(const float4*)(Bp + (size_t)(k0 + 16) * ldb);
        }
#pragma unroll
        for (int kk = 0; kk < 16; kk++) {
            ulonglong2 a01 = *(const ulonglong2*)&AsD[kk * 136 + ty * 8];
            ulonglong2 a23 = *(const ulonglong2*)&AsD[kk * 136 + ty * 8 + 4];
            ulonglong2 bp  = *(const ulonglong2*)&Bs[kk * 68 + tx * 4];
            ffma2(acc[0][0].u, a01.x, bp.x); ffma2(acc[0][1].u, a01.x, bp.y);
            ffma2(acc[1][0].u, a01.y, bp.x); ffma2(acc[1][1].u, a01.y, bp.y);
            ffma2(acc[2][0].u, a23.x, bp.x); ffma2(acc[2][1].u, a23.x, bp.y);
            ffma2(acc[3][0].u, a23.y, bp.x); ffma2(acc[3][1].u, a23.y, bp.y);
        }
        __syncthreads();
    }
    // epilogue: row r = ty*4+p, cols tx*4..+3 (n-pairs live in lanes)
#pragma unroll
    for (int p = 0; p < 4; p++) {
        int r = ty * 4 + p;
        float o0 = alpha * acc[p][0].f.x, o1 = alpha * acc[p][0].f.y;
        float o2 = alpha * acc[p][1].f.x, o3 = alpha * acc[p][1].f.y;
        if (Cin) {
            o0 += Cin[(size_t)r * ldc + tx * 4 + 0];
            o1 += Cin[(size_t)r * ldc + tx * 4 + 1];
            o2 += Cin[(size_t)r * ldc + tx * 4 + 2];
            o3 += Cin[(size_t)r * ldc + tx * 4 + 3];
        }
        float4 v4 = make_float4(o0, o1, o2, o3);
        *(float4*)&D1[(size_t)r * ldd + tx * 4] = v4;
        if (D2) *(float4*)&D2[(size_t)r * ldd + tx * 4] = v4;
    }
}

// ---------------- Newton-Schulz strip (proven R6..R13) ----------------------------
__device__ __forceinline__ void newton_strip(const float* __restrict__ Xin,
                                             float* __restrict__ Xout, float* sm)
{
    float* Qs = sm;           // [128][20]
    float* Xs = sm + 2560;    // [128][4]
    float* Ts = sm + 3072;    // [128][4]
    const int tid = threadIdx.x;
    const int J = blockIdx.x * 4;
    for (int i = tid; i < 512; i += 256) {
        int r = i >> 2, jj = i & 3;
        Xs[i] = Xin[r * NC + J + jj];
    }
    __syncthreads();
    const int r = tid >> 1, jh = (tid & 1) * 2;
    float t0 = 0.f, t1 = 0.f;
    for (int k0 = 0; k0 < NC; k0 += 16) {
        for (int i = tid; i < 512; i += 256) {
            int rr = i >> 2, q4 = i & 3;
            *(float4*)&Qs[rr * 20 + q4 * 4] =
                *(const float4*)&g_Q[(size_t)(NS + rr) * ND + NS + k0 + q4 * 4];
        }
        __syncthreads();
#pragma unroll
        for (int kk = 0; kk < 16; kk++) {
            float a = Qs[r * 20 + kk];
            t0 = fmaf(a, Xs[(k0 + kk) * 4 + jh], t0);
            t1 = fmaf(a, Xs[(k0 + kk) * 4 + jh + 1], t1);
        }
        __syncthreads();
    }
    Ts[r * 4 + jh] = t0; Ts[r * 4 + jh + 1] = t1;
    __syncthreads();
    float x0 = 0.f, x1 = 0.f;
    for (int k0 = 0; k0 < NC; k0 += 16) {
        for (int i = tid; i < 512; i += 256) {
            int rr = i >> 2, q4 = i & 3;
            *(float4*)&Qs[rr * 20 + q4 * 4] =
                *(const float4*)&Xin[rr * NC + k0 + q4 * 4];
        }
        __syncthreads();
#pragma unroll
        for (int kk = 0; kk < 16; kk++) {
            float a = Qs[r * 20 + kk];
            x0 = fmaf(a, Ts[(k0 + kk) * 4 + jh], x0);
            x1 = fmaf(a, Ts[(k0 + kk) * 4 + jh + 1], x1);
        }
        __syncthreads();
    }
    Xout[r * NC + J + jh]     = 2.f * Xs[r * 4 + jh]     - x0;
    Xout[r * NC + J + jh + 1] = 2.f * Xs[r * 4 + jh + 1] - x1;
}

// ---------------- the persistent kernel -------------------------------------------
__global__ void __launch_bounds__(256, 1) lqr_kernel(
    const float* __restrict__ F, const float* __restrict__ f,
    const float* __restrict__ C, const float* __restrict__ c,
    float* __restrict__ out)
{
    __shared__ __align__(16) float sm[3600];
    __shared__ float red[264];
    const int bid = blockIdx.x, tid = threadIdx.x, nb = gridDim.x;
    float* outK = out;
    float* outk = outK + (size_t)TT * NC * NS;
    float* outV = outk + (size_t)TT * NC;
    float* outv = outV + (size_t)TT * NS * NS;
    float* outc = outv + (size_t)TT * NS;

    // ---- init: V = C[:n,:n], v = c[:n], const = 0 ----
    for (int i = bid * 256 + tid; i < NS * NS; i += nb * 256) {
        int r = i >> 9, cq = i & (NS - 1);
        g_V[i] = C[(size_t)r * ND + cq];
    }
    if (bid == nb - 1) {
        for (int i = tid; i < NS; i += 256) g_v[i] = c[i];
        if (tid == 0) g_cst = 0.f;
    }
    gsync();

    int cur = 0;
    for (int s = 0; s < TT; s++) {
        const int t = TT - 1 - s;

        // ---- Phase A: FVt = V @ F (80 tiles 64x64, K=512); w = V @ f ----
        if (bid < 80) {
            const int n0 = (bid / 10) * 64, m0 = (bid % 10) * 64;
            gemmKB(g_V + n0, NS, F + m0, ND, nullptr, 0,
                   g_FVt + (size_t)n0 * ND + m0, nullptr, ND,
                   NS, 1.f, sm);
        } else if (bid < 144) {
            int row = (bid - 80) * 8 + (tid >> 5);
            int lane = tid & 31;
            if (row < NS) {
                float ssum = 0.f;
                for (int i = lane; i < NS; i += 32) ssum += g_V[row * NS + i] * f[i];
                for (int o = 16; o; o >>= 1) ssum += __shfl_down_sync(~0u, ssum, o);
                if (!lane) g_w[row] = ssum;
            }
        }
        gsync();

        // ---- Phase B: Q = C + FV @ F (100 tiles); q over 40 CTAs (k-split) ----
        if (bid < 100) {
            const int m0 = (bid / 10) * 64, n0 = (bid % 10) * 64;
            gemmKB(g_FVt + m0, ND, F + n0, ND,
                   C + (size_t)m0 * ND + n0, ND,
                   g_Q + (size_t)m0 * ND + n0, nullptr, ND,
                   NS, 1.f, sm);
        } else if (bid < 140) {
            // q[a] = c[a] + sum_k FVt[k][a] f[k] + F[k][a] v[k]
            // 40 CTAs x 16 columns; 16 k-chunks of 32 -> short latency chains
            const int a0 = (bid - 100) * 16;
            const int ci = tid & 15, kp = tid >> 4;
            const int kb = kp * 32;
            float part = 0.f;
#pragma unroll 4
            for (int i = 0; i < 32; i++) {
                int k = kb + i;
                part += g_FVt[(size_t)k * ND + a0 + ci] * f[k]
                      + F[(size_t)k * ND + a0 + ci] * g_v[k];
            }
            sm[tid] = part;
            __syncthreads();
            if (tid < 16) {
                float ssum = 0.f;
#pragma unroll
                for (int p = 0; p < 16; p++) ssum += sm[p * 16 + tid];
                g_q[a0 + tid] = c[a0 + tid] + ssum;
            }
        }
        gsync();

        // ---- Phase C0 (s==0): X0 = I / ||Quu||_inf ----
        if (s == 0) {
            if (bid == 0) {
                float m = 0.f;
                if (tid < NC) {
                    float ssum = 0.f;
                    const float* Qr = &g_Q[(size_t)(NS + tid) * ND + NS];
                    for (int j = 0; j < NC; j++) ssum += fabsf(Qr[j]);
                    m = ssum;
                }
                red[tid] = m; __syncthreads();
                for (int st = 128; st; st >>= 1) {
                    if (tid < st) red[tid] = fmaxf(red[tid], red[tid + st]);
                    __syncthreads();
                }
                float inv = 1.f / red[0];
                __syncthreads();
                for (int i = tid; i < NC * NC; i += 256) {
                    int r2 = i >> 7, c2 = i & 127;
                    g_X[0][i] = (r2 == c2) ? inv : 0.f;
                }
            }
            gsync();
        }

        // ---- Phase C: Newton-Schulz (warm-started) ----
        int niter = (s == 0) ? 20 : ((s < 8) ? 4 : 2);
        for (int it = 0; it < niter; it++) {
            if (bid < 32) newton_strip(g_X[cur], g_X[cur ^ 1], sm);
            cur ^= 1;
            gsync();
        }

        // ---- Phase D: K = -X @ Qux (16 tiles, K=128); bid16: k, const ----
        if (bid < 16) {
            const int m0 = (bid >> 3) * 64, n0 = (bid & 7) * 64;
            gemmKB(g_X[cur] + m0, NC,
                   g_Q + (size_t)NS * ND + n0, ND,
                   nullptr, 0,
                   g_K + (size_t)m0 * NS + n0,
                   outK + (size_t)t * NC * NS + (size_t)m0 * NS + n0, NS,
                   NC, -1.f, sm);
        } else if (bid == 16) {
            float* ksh = sm; float* quk = sm + 132;
            float kv = 0.f;
            if (tid < NC) {
                // k[m] = -sum_j X[j][m] qu[j]   (X ~symmetric; column = coalesced)
                const float* Xc = g_X[cur];
#pragma unroll 8
                for (int j = 0; j < NC; j++)
                    kv += Xc[(size_t)j * NC + tid] * g_q[NS + j];
                kv = -kv;
                ksh[tid] = kv; g_k[tid] = kv; outk[(size_t)t * NC + tid] = kv;
            }
            __syncthreads();
            if (tid < NC) {
                // quk[m] = sum_j Quu[j][m] ksh[j]  (Quu symmetric; coalesced)
                float qk = 0.f;
#pragma unroll 8
                for (int j = 0; j < NC; j++)
                    qk = fmaf(g_Q[(size_t)(NS + j) * ND + NS + tid], ksh[j], qk);
                quk[tid] = qk;
            }
            __syncthreads();
            float pp1 = 0.f, pp2 = 0.f, pp3 = 0.f, pp4 = 0.f;
            for (int i = tid; i < NC; i += 256) { pp1 += ksh[i] * quk[i]; pp2 += ksh[i] * g_q[NS + i]; }
            for (int i = tid; i < NS; i += 256) { pp3 += f[i] * g_w[i];   pp4 += f[i] * g_v[i]; }
            float parts[4] = {pp1, pp2, pp3, pp4};
            float res[4];
            for (int qd = 0; qd < 4; qd++) {
                red[tid] = parts[qd]; __syncthreads();
                for (int st = 128; st; st >>= 1) {
                    if (tid < st) red[tid] += red[tid + st];
                    __syncthreads();
                }
                res[qd] = red[0]; __syncthreads();
            }
            if (tid == 0) {
                float cn = g_cst + 0.5f * res[0] + res[1] + 0.5f * res[2] + res[3];
                g_cst = cn;
                outc[t] = cn;
            }
        }
        gsync();

        // ---- Phase E: Vn = Qxx + Qxu @ K (64 tiles, K=128); vn over 32 CTAs ----
        if (bid < 64) {
            const int m0 = (bid >> 3) * 64, n0 = (bid & 7) * 64;
            gemmKB(g_Q + (size_t)NS * ND + m0, ND,
                   g_K + n0, NS,
                   g_Q + (size_t)m0 * ND + n0, ND,
                   g_V + (size_t)m0 * NS + n0,
                   outV + (size_t)t * NS * NS + (size_t)m0 * NS + n0, NS,
                   NC, 1.f, sm);
        } else if (bid < 96) {
            // vn[x] = qx[x] + sum_j Qux[j][x] k[j] ; 32 CTAs x 16 cols, j-split
            const int x0 = (bid - 64) * 16;
            const int ci = tid & 15, jp = tid >> 4;
            float part = 0.f;
#pragma unroll
            for (int i = 0; i < 8; i++) {
                int j = jp * 8 + i;
                part += g_Q[(size_t)(NS + j) * ND + x0 + ci] * g_k[j];
            }
            sm[tid] = part;
            __syncthreads();
            if (tid < 16) {
                float ssum = 0.f;
#pragma unroll
                for (int p = 0; p < 16; p++) ssum += sm[p * 16 + tid];
                float val = g_q[x0 + tid] + ssum;
                g_v[x0 + tid] = val;
                outv[(size_t)t * NS + x0 + tid] = val;
            }
        }
        gsync();
    }
}

// ---------------- host -------------------------------------------------------------
extern "C" void kernel_launch(void* const* d_in, const int* in_sizes, int n_in,
                              void* d_out, int out_size) {
    (void)in_sizes; (void)n_in; (void)out_size;
    const float* F = (const float*)d_in[0];
    const float* f = (const float*)d_in[1];
    const float* C = (const float*)d_in[2];
    const float* c = (const float*)d_in[3];
    lqr_kernel<<<NBLK, 256>>>(F, f, C, c, (float*)d_out);
}

// round 15
// speedup vs baseline: 1.9078x; 1.1130x over previous
#include <cuda_runtime.h>
#include <cstdint>

#define NS 512
#define NC 128
#define ND 640
#define TT 256
#define NBLK 148
// gemm double buffers: 2 x (AsD[16][136] + Bs[16][68]) = 2*3264 floats
// newton resident: Qres[128][132] + Xres[128][132] + Xs[512] + Ts[512] = 34816 floats
#define DSMEM (34816 * 4)

// ---------------- persistent device state (no allocation allowed) ----------------
__device__ __align__(16) float g_V[NS * NS];     // carry V (512x512), symmetric
__device__ __align__(16) float g_FVt[NS * ND];   // FVt[k][m] = FV[m][k] (512x640)
__device__ __align__(16) float g_Q[ND * ND];     // Q (640x640), symmetric
__device__ __align__(16) float g_K[NC * NS];     // K (128x512)
__device__ __align__(16) float g_X[2][NC * NC];  // Newton ping-pong, ~symmetric
__device__ float g_q[ND], g_w[NS], g_v[NS], g_k[NC], g_cst;
__device__ unsigned g_arrive;
__device__ volatile unsigned g_gen;

// ---------------- grid-wide barrier ----------------------------------------------
__device__ __forceinline__ void gsync() {
    __syncthreads();
    if (threadIdx.x == 0) {
        unsigned gen = g_gen;
        __threadfence();
        if (atomicAdd(&g_arrive, 1u) == gridDim.x - 1) {
            g_arrive = 0;
            __threadfence();
            g_gen = gen + 1;
        } else {
            while (g_gen == gen) { __nanosleep(64); }
        }
        __threadfence();
    }
    __syncthreads();
}

// ---------------- packed f32x2 helpers --------------------------------------------
union UF2 { unsigned long long u; float2 f; };
__device__ __forceinline__ void ffma2(unsigned long long& d,
                                      unsigned long long a, unsigned long long b) {
    asm("fma.rn.f32x2 %0, %1, %2, %0;" : "+l"(d) : "l"(a), "l"(b));
}

// ---------------- 64x64 tile GEMM: double-buffered smem + slab-ahead prefetch -----
// D = alpha * (sum_k A[k][m-win] * B[k][n-win]) + Cin.  A/B natural [k][col] layout,
// pre-offset to the tile's column window. Inner loop & epilogue identical to R14.
__device__ __forceinline__ void gemmKB(
    const float* __restrict__ Asrc, int lda,
    const float* __restrict__ Bsrc, int ldb,
    const float* __restrict__ Cin, int ldc,
    float* __restrict__ D1, float* __restrict__ D2, int ldd,
    int KC, float alpha, float* smf)
{
    const int tid = threadIdx.x;
    const int tx = tid & 15, ty = tid >> 4;
    const int sr = tid >> 4, sc = (tid & 15) << 2;   // staging row / col
    const float* Ap = Asrc + (size_t)sr * lda + sc;
    const float* Bp = Bsrc + (size_t)sr * ldb + sc;
    const int nsl = KC >> 4;
    UF2 acc[4][2];
#pragma unroll
    for (int p = 0; p < 4; p++) { acc[p][0].u = 0ull; acc[p][1].u = 0ull; }

    float4 av = *(const float4*)Ap;
    float4 bv = *(const float4*)Bp;
    // store slab 0 -> buffer 0
    {
        float* A0 = smf;            // [16][136]
        float* B0 = smf + 2176;     // [16][68]
        *(float4*)&A0[sr * 136 + 2 * sc]     = make_float4(av.x, av.x, av.y, av.y);
        *(float4*)&A0[sr * 136 + 2 * sc + 4] = make_float4(av.z, av.z, av.w, av.w);
        *(float4*)&B0[sr * 68 + sc] = bv;
    }
    __syncthreads();
    if (nsl > 1) {   // prefetch slab 1
        av = *(const float4*)(Ap + (size_t)16 * lda);
        bv = *(const float4*)(Bp + (size_t)16 * ldb);
    }
    for (int i = 0; i < nsl; i++) {
        const float* AsD = smf + (i & 1) * 3264;
        const float* Bs  = AsD + 2176;
#pragma unroll
        for (int kk = 0; kk < 16; kk++) {
            ulonglong2 a01 = *(const ulonglong2*)&AsD[kk * 136 + ty * 8];
            ulonglong2 a23 = *(const ulonglong2*)&AsD[kk * 136 + ty * 8 + 4];
            ulonglong2 bp  = *(const ulonglong2*)&Bs[kk * 68 + tx * 4];
            ffma2(acc[0][0].u, a01.x, bp.x); ffma2(acc[0][1].u, a01.x, bp.y);
            ffma2(acc[1][0].u, a01.y, bp.x); ffma2(acc[1][1].u, a01.y, bp.y);
            ffma2(acc[2][0].u, a23.x, bp.x); ffma2(acc[2][1].u, a23.x, bp.y);
            ffma2(acc[3][0].u, a23.y, bp.x); ffma2(acc[3][1].u, a23.y, bp.y);
        }
        if (i + 1 < nsl) {   // store prefetched slab i+1 into the other buffer
            float* An = smf + ((i + 1) & 1) * 3264;
            float* Bn = An + 2176;
            *(float4*)&An[sr * 136 + 2 * sc]     = make_float4(av.x, av.x, av.y, av.y);
            *(float4*)&An[sr * 136 + 2 * sc + 4] = make_float4(av.z, av.z, av.w, av.w);
            *(float4*)&Bn[sr * 68 + sc] = bv;
        }
        __syncthreads();
        if (i + 2 < nsl) {   // prefetch slab i+2 (consumed after next compute)
            av = *(const float4*)(Ap + (size_t)(i + 2) * 16 * lda);
            bv = *(const float4*)(Bp + (size_t)(i + 2) * 16 * ldb);
        }
    }
    // epilogue: row r = ty*4+p, cols tx*4..+3
#pragma unroll
    for (int p = 0; p < 4; p++) {
        int r = ty * 4 + p;
        float o0 = alpha * acc[p][0].f.x, o1 = alpha * acc[p][0].f.y;
        float o2 = alpha * acc[p][1].f.x, o3 = alpha * acc[p][1].f.y;
        if (Cin) {
            o0 += Cin[(size_t)r * ldc + tx * 4 + 0];
            o1 += Cin[(size_t)r * ldc + tx * 4 + 1];
            o2 += Cin[(size_t)r * ldc + tx * 4 + 2];
            o3 += Cin[(size_t)r * ldc + tx * 4 + 3];
        }
        float4 v4 = make_float4(o0, o1, o2, o3);
        *(float4*)&D1[(size_t)r * ldd + tx * 4] = v4;
        if (D2) *(float4*)&D2[(size_t)r * ldd + tx * 4] = v4;
    }
}

// ---------------- Newton-Schulz strip, resident operands --------------------------
// Qres (staged once per step) and Xres (per iteration) live in smem; both passes
// are pure LDS+FMA. Accumulation order k=0..127 identical to all prior rounds.
#define QRES_OFF 0
#define XRES_OFF 16896
#define XS_OFF   33792
#define TS_OFF   34304

__device__ __forceinline__ void newton_stage_Q(float* smf) {
    const int tid = threadIdx.x;
    float* Qres = smf + QRES_OFF;
    for (int idx = tid; idx < 4096; idx += 256) {
        int row = idx >> 5, c4 = (idx & 31) << 2;
        *(float4*)&Qres[row * 132 + c4] =
            *(const float4*)&g_Q[(size_t)(NS + row) * ND + NS + c4];
    }
}

__device__ __forceinline__ void newton_strip(const float* __restrict__ Xin,
                                             float* __restrict__ Xout, float* smf)
{
    float* Qres = smf + QRES_OFF;   // [128][132]
    float* Xres = smf + XRES_OFF;   // [128][132]
    float* Xs   = smf + XS_OFF;     // [128][4]
    float* Ts   = smf + TS_OFF;     // [128][4]
    const int tid = threadIdx.x;
    const int J = blockIdx.x * 4;
    for (int idx = tid; idx < 4096; idx += 256) {
        int row = idx >> 5, c4 = (idx & 31) << 2;
        *(float4*)&Xres[row * 132 + c4] = *(const float4*)&Xin[row * NC + c4];
    }
    for (int i = tid; i < 512; i += 256) {
        int r = i >> 2, jj = i & 3;
        Xs[i] = Xin[r * NC + J + jj];
    }
    __syncthreads();
    const int r = tid >> 1, jh = (tid & 1) * 2;
    float t0 = 0.f, t1 = 0.f;
#pragma unroll 8
    for (int k = 0; k < NC; k++) {
        float a = Qres[r * 132 + k];
        t0 = fmaf(a, Xs[k * 4 + jh], t0);
        t1 = fmaf(a, Xs[k * 4 + jh + 1], t1);
    }
    Ts[r * 4 + jh] = t0; Ts[r * 4 + jh + 1] = t1;
    __syncthreads();
    float x0 = 0.f, x1 = 0.f;
#pragma unroll 8
    for (int k = 0; k < NC; k++) {
        float a = Xres[r * 132 + k];
        x0 = fmaf(a, Ts[k * 4 + jh], x0);
        x1 = fmaf(a, Ts[k * 4 + jh + 1], x1);
    }
    Xout[r * NC + J + jh]     = 2.f * Xs[r * 4 + jh]     - x0;
    Xout[r * NC + J + jh + 1] = 2.f * Xs[r * 4 + jh + 1] - x1;
    __syncthreads();   // protect Xres/Ts before next iteration restages
}

// ---------------- the persistent kernel -------------------------------------------
__global__ void __launch_bounds__(256, 1) lqr_kernel(
    const float* __restrict__ F, const float* __restrict__ f,
    const float* __restrict__ C, const float* __restrict__ c,
    float* __restrict__ out)
{
    extern __shared__ __align__(16) float smf[];
    __shared__ __align__(16) float sm[3600];
    __shared__ float red[264];
    const int bid = blockIdx.x, tid = threadIdx.x, nb = gridDim.x;
    float* outK = out;
    float* outk = outK + (size_t)TT * NC * NS;
    float* outV = outk + (size_t)TT * NC;
    float* outv = outV + (size_t)TT * NS * NS;
    float* outc = outv + (size_t)TT * NS;

    // ---- init: V = C[:n,:n], v = c[:n], const = 0 ----
    for (int i = bid * 256 + tid; i < NS * NS; i += nb * 256) {
        int r = i >> 9, cq = i & (NS - 1);
        g_V[i] = C[(size_t)r * ND + cq];
    }
    if (bid == nb - 1) {
        for (int i = tid; i < NS; i += 256) g_v[i] = c[i];
        if (tid == 0) g_cst = 0.f;
    }
    gsync();

    int cur = 0;
    for (int s = 0; s < TT; s++) {
        const int t = TT - 1 - s;

        // ---- Phase A: FVt = V @ F (80 tiles 64x64, K=512); w = V @ f ----
        if (bid < 80) {
            const int n0 = (bid / 10) * 64, m0 = (bid % 10) * 64;
            gemmKB(g_V + n0, NS, F + m0, ND, nullptr, 0,
                   g_FVt + (size_t)n0 * ND + m0, nullptr, ND,
                   NS, 1.f, smf);
        } else if (bid < 144) {
            int row = (bid - 80) * 8 + (tid >> 5);
            int lane = tid & 31;
            if (row < NS) {
                float ssum = 0.f;
                for (int i = lane; i < NS; i += 32) ssum += g_V[row * NS + i] * f[i];
                for (int o = 16; o; o >>= 1) ssum += __shfl_down_sync(~0u, ssum, o);
                if (!lane) g_w[row] = ssum;
            }
        }
        gsync();

        // ---- Phase B: Q = C + FV @ F (100 tiles); q over 40 CTAs (k-split) ----
        if (bid < 100) {
            const int m0 = (bid / 10) * 64, n0 = (bid % 10) * 64;
            gemmKB(g_FVt + m0, ND, F + n0, ND,
                   C + (size_t)m0 * ND + n0, ND,
                   g_Q + (size_t)m0 * ND + n0, nullptr, ND,
                   NS, 1.f, smf);
        } else if (bid < 140) {
            const int a0 = (bid - 100) * 16;
            const int ci = tid & 15, kp = tid >> 4;
            const int kb = kp * 32;
            float part = 0.f;
#pragma unroll 4
            for (int i = 0; i < 32; i++) {
                int k = kb + i;
                part += g_FVt[(size_t)k * ND + a0 + ci] * f[k]
                      + F[(size_t)k * ND + a0 + ci] * g_v[k];
            }
            sm[tid] = part;
            __syncthreads();
            if (tid < 16) {
                float ssum = 0.f;
#pragma unroll
                for (int p = 0; p < 16; p++) ssum += sm[p * 16 + tid];
                g_q[a0 + tid] = c[a0 + tid] + ssum;
            }
        }
        gsync();

        // ---- Phase C0 (s==0): X0 = I / ||Quu||_inf ----
        if (s == 0) {
            if (bid == 0) {
                float m = 0.f;
                if (tid < NC) {
                    float ssum = 0.f;
                    const float* Qr = &g_Q[(size_t)(NS + tid) * ND + NS];
                    for (int j = 0; j < NC; j++) ssum += fabsf(Qr[j]);
                    m = ssum;
                }
                red[tid] = m; __syncthreads();
                for (int st = 128; st; st >>= 1) {
                    if (tid < st) red[tid] = fmaxf(red[tid], red[tid + st]);
                    __syncthreads();
                }
                float inv = 1.f / red[0];
                __syncthreads();
                for (int i = tid; i < NC * NC; i += 256) {
                    int r2 = i >> 7, c2 = i & 127;
                    g_X[0][i] = (r2 == c2) ? inv : 0.f;
                }
            }
            gsync();
        }

        // ---- Phase C: Newton-Schulz (warm-started), Quu resident per step ----
        if (bid < 32) newton_stage_Q(smf);
        int niter = (s == 0) ? 20 : ((s < 8) ? 4 : 2);
        for (int it = 0; it < niter; it++) {
            if (bid < 32) newton_strip(g_X[cur], g_X[cur ^ 1], smf);
            cur ^= 1;
            gsync();
        }

        // ---- Phase D: K = -X @ Qux (16 tiles, K=128); bid16: k, const ----
        if (bid < 16) {
            const int m0 = (bid >> 3) * 64, n0 = (bid & 7) * 64;
            gemmKB(g_X[cur] + m0, NC,
                   g_Q + (size_t)NS * ND + n0, ND,
                   nullptr, 0,
                   g_K + (size_t)m0 * NS + n0,
                   outK + (size_t)t * NC * NS + (size_t)m0 * NS + n0, NS,
                   NC, -1.f, smf);
        } else if (bid == 16) {
            float* ksh = sm; float* quk = sm + 132;
            float kv = 0.f;
            if (tid < NC) {
                const float* Xc = g_X[cur];
#pragma unroll 8
                for (int j = 0; j < NC; j++)
                    kv += Xc[(size_t)j * NC + tid] * g_q[NS + j];
                kv = -kv;
                ksh[tid] = kv; g_k[tid] = kv; outk[(size_t)t * NC + tid] = kv;
            }
            __syncthreads();
            if (tid < NC) {
                float qk = 0.f;
#pragma unroll 8
                for (int j = 0; j < NC; j++)
                    qk = fmaf(g_Q[(size_t)(NS + j) * ND + NS + tid], ksh[j], qk);
                quk[tid] = qk;
            }
            __syncthreads();
            float pp1 = 0.f, pp2 = 0.f, pp3 = 0.f, pp4 = 0.f;
            for (int i = tid; i < NC; i += 256) { pp1 += ksh[i] * quk[i]; pp2 += ksh[i] * g_q[NS + i]; }
            for (int i = tid; i < NS; i += 256) { pp3 += f[i] * g_w[i];   pp4 += f[i] * g_v[i]; }
            float parts[4] = {pp1, pp2, pp3, pp4};
            float res[4];
            for (int qd = 0; qd < 4; qd++) {
                red[tid] = parts[qd]; __syncthreads();
                for (int st = 128; st; st >>= 1) {
                    if (tid < st) red[tid] += red[tid + st];
                    __syncthreads();
                }
                res[qd] = red[0]; __syncthreads();
            }
            if (tid == 0) {
                float cn = g_cst + 0.5f * res[0] + res[1] + 0.5f * res[2] + res[3];
                g_cst = cn;
                outc[t] = cn;
            }
        }
        gsync();

        // ---- Phase E: Vn = Qxx + Qxu @ K (64 tiles, K=128); vn over 32 CTAs ----
        if (bid < 64) {
            const int m0 = (bid >> 3) * 64, n0 = (bid & 7) * 64;
            gemmKB(g_Q + (size_t)NS * ND + m0, ND,
                   g_K + n0, NS,
                   g_Q + (size_t)m0 * ND + n0, ND,
                   g_V + (size_t)m0 * NS + n0,
                   outV + (size_t)t * NS * NS + (size_t)m0 * NS + n0, NS,
                   NC, 1.f, smf);
        } else if (bid < 96) {
            const int x0 = (bid - 64) * 16;
            const int ci = tid & 15, jp = tid >> 4;
            float part = 0.f;
#pragma unroll
            for (int i = 0; i < 8; i++) {
                int j = jp * 8 + i;
                part += g_Q[(size_t)(NS + j) * ND + x0 + ci] * g_k[j];
            }
            sm[tid] = part;
            __syncthreads();
            if (tid < 16) {
                float ssum = 0.f;
#pragma unroll
                for (int p = 0; p < 16; p++) ssum += sm[p * 16 + tid];
                float val = g_q[x0 + tid] + ssum;
                g_v[x0 + tid] = val;
                outv[(size_t)t * NS + x0 + tid] = val;
            }
        }
        gsync();
    }
}

// ---------------- host -------------------------------------------------------------
extern "C" void kernel_launch(void* const* d_in, const int* in_sizes, int n_in,
                              void* d_out, int out_size) {
    (void)in_sizes; (void)n_in; (void)out_size;
    const float* F = (const float*)d_in[0];
    const float* f = (const float*)d_in[1];
    const float* C = (const float*)d_in[2];
    const float* c = (const float*)d_in[3];
    cudaFuncSetAttribute(lqr_kernel, cudaFuncAttributeMaxDynamicSharedMemorySize, DSMEM);
    lqr_kernel<<<NBLK, 256, DSMEM>>>(F, f, C, c, (float*)d_out);
}

// round 16
// speedup vs baseline: 1.9199x; 1.0063x over previous
#include <cuda_runtime.h>
#include <cstdint>

#define NS 512
#define NC 128
#define ND 640
#define TT 256
#define NBLK 148
// newton resident (34816 floats) dominates; gemmBig needs 2*5312=10624 floats
#define DSMEM (34816 * 4)

// ---------------- persistent device state (no allocation allowed) ----------------
__device__ __align__(16) float g_V[NS * NS];        // carry V, symmetric
__device__ __align__(16) float g_FVp[2][NS * ND];   // FVt partials (k-chunks)
__device__ __align__(16) float g_Qp[2][ND * ND];    // Q partials (k-chunks)
__device__ __align__(16) float g_Q[ND * ND];        // Q combined, symmetric
__device__ __align__(16) float g_K[NC * NS];        // K (128x512)
__device__ __align__(16) float g_X[2][NC * NC];     // Newton ping-pong
__device__ float g_q[ND], g_w[NS], g_v[NS], g_k[NC], g_cst;
__device__ unsigned g_arrive;
__device__ volatile unsigned g_gen;

// ---------------- grid-wide barrier ----------------------------------------------
__device__ __forceinline__ void gsync() {
    __syncthreads();
    if (threadIdx.x == 0) {
        unsigned gen = g_gen;
        __threadfence();
        if (atomicAdd(&g_arrive, 1u) == gridDim.x - 1) {
            g_arrive = 0;
            __threadfence();
            g_gen = gen + 1;
        } else {
            while (g_gen == gen) { __nanosleep(64); }
        }
        __threadfence();
    }
    __syncthreads();
}

// ---------------- packed f32x2 helpers --------------------------------------------
union UF2 { unsigned long long u; float2 f; };
__device__ __forceinline__ void ffma2(unsigned long long& d,
                                      unsigned long long a, unsigned long long b) {
    asm("fma.rn.f32x2 %0, %1, %2, %0;" : "+l"(d) : "l"(a), "l"(b));
}

// ---------------- 128x64 tile GEMM (256 thr, 8x2-f32x2/thread, double-buffered) ---
// D1 = alpha * sum_k (A1[k][m-win] (+A2)) * B[k][n-win].  Natural [k][col] layouts.
// Buffers: buf b at smf + b*5312:  AsD[16][264] (dup'd A), Bs[16][68] at +4224.
__device__ __forceinline__ void gemmBig(
    const float* __restrict__ A1, const float* __restrict__ A2, int lda,
    const float* __restrict__ Bsrc, int ldb,
    float* __restrict__ D1, int ldd,
    int KC, float alpha, float* smf)
{
    const int tid = threadIdx.x;
    const int tx = tid & 15, ty = tid >> 4;
    const int sr = tid >> 4;
    const int sc8 = (tid & 15) << 3;
    const int sc4 = (tid & 15) << 2;
    const float* Ap1 = A1 + (size_t)sr * lda + sc8;
    const float* Ap2 = A2 ? (A2 + (size_t)sr * lda + sc8) : (const float*)0;
    const float* Bp  = Bsrc + (size_t)sr * ldb + sc4;
    const int nsl = KC >> 4;
    UF2 acc[8][2];
#pragma unroll
    for (int p = 0; p < 8; p++) { acc[p][0].u = 0ull; acc[p][1].u = 0ull; }

    float4 av0 = *(const float4*)Ap1;
    float4 av1 = *(const float4*)(Ap1 + 4);
    if (Ap2) {
        float4 e0 = *(const float4*)Ap2, e1 = *(const float4*)(Ap2 + 4);
        av0.x += e0.x; av0.y += e0.y; av0.z += e0.z; av0.w += e0.w;
        av1.x += e1.x; av1.y += e1.y; av1.z += e1.z; av1.w += e1.w;
    }
    float4 bv = *(const float4*)Bp;
    // store slab 0 -> buffer 0
    {
        float* AsD = smf; float* Bs = smf + 4224;
        float* w = &AsD[sr * 264 + 2 * sc8];
        *(float4*)(w + 0)  = make_float4(av0.x, av0.x, av0.y, av0.y);
        *(float4*)(w + 4)  = make_float4(av0.z, av0.z, av0.w, av0.w);
        *(float4*)(w + 8)  = make_float4(av1.x, av1.x, av1.y, av1.y);
        *(float4*)(w + 12) = make_float4(av1.z, av1.z, av1.w, av1.w);
        *(float4*)&Bs[sr * 68 + sc4] = bv;
    }
    __syncthreads();
    if (nsl > 1) {
        av0 = *(const float4*)(Ap1 + (size_t)16 * lda);
        av1 = *(const float4*)(Ap1 + (size_t)16 * lda + 4);
        if (Ap2) {
            float4 e0 = *(const float4*)(Ap2 + (size_t)16 * lda);
            float4 e1 = *(const float4*)(Ap2 + (size_t)16 * lda + 4);
            av0.x += e0.x; av0.y += e0.y; av0.z += e0.z; av0.w += e0.w;
            av1.x += e1.x; av1.y += e1.y; av1.z += e1.z; av1.w += e1.w;
        }
        bv = *(const float4*)(Bp + (size_t)16 * ldb);
    }
    for (int i = 0; i < nsl; i++) {
        const float* AsD = smf + (i & 1) * 5312;
        const float* Bs  = AsD + 4224;
#pragma unroll
        for (int kk = 0; kk < 16; kk++) {
            const float* Ar = &AsD[kk * 264 + ty * 16];
            ulonglong2 a01 = *(const ulonglong2*)(Ar + 0);
            ulonglong2 a23 = *(const ulonglong2*)(Ar + 4);
            ulonglong2 a45 = *(const ulonglong2*)(Ar + 8);
            ulonglong2 a67 = *(const ulonglong2*)(Ar + 12);
            ulonglong2 bp  = *(const ulonglong2*)&Bs[kk * 68 + tx * 4];
            ffma2(acc[0][0].u, a01.x, bp.x); ffma2(acc[0][1].u, a01.x, bp.y);
            ffma2(acc[1][0].u, a01.y, bp.x); ffma2(acc[1][1].u, a01.y, bp.y);
            ffma2(acc[2][0].u, a23.x, bp.x); ffma2(acc[2][1].u, a23.x, bp.y);
            ffma2(acc[3][0].u, a23.y, bp.x); ffma2(acc[3][1].u, a23.y, bp.y);
            ffma2(acc[4][0].u, a45.x, bp.x); ffma2(acc[4][1].u, a45.x, bp.y);
            ffma2(acc[5][0].u, a45.y, bp.x); ffma2(acc[5][1].u, a45.y, bp.y);
            ffma2(acc[6][0].u, a67.x, bp.x); ffma2(acc[6][1].u, a67.x, bp.y);
            ffma2(acc[7][0].u, a67.y, bp.x); ffma2(acc[7][1].u, a67.y, bp.y);
        }
        if (i + 1 < nsl) {
            float* An = smf + ((i + 1) & 1) * 5312;
            float* Bn = An + 4224;
            float* w = &An[sr * 264 + 2 * sc8];
            *(float4*)(w + 0)  = make_float4(av0.x, av0.x, av0.y, av0.y);
            *(float4*)(w + 4)  = make_float4(av0.z, av0.z, av0.w, av0.w);
            *(float4*)(w + 8)  = make_float4(av1.x, av1.x, av1.y, av1.y);
            *(float4*)(w + 12) = make_float4(av1.z, av1.z, av1.w, av1.w);
            *(float4*)&Bn[sr * 68 + sc4] = bv;
        }
        __syncthreads();
        if (i + 2 < nsl) {
            size_t off = (size_t)(i + 2) * 16;
            av0 = *(const float4*)(Ap1 + off * lda);
            av1 = *(const float4*)(Ap1 + off * lda + 4);
            if (Ap2) {
                float4 e0 = *(const float4*)(Ap2 + off * lda);
                float4 e1 = *(const float4*)(Ap2 + off * lda + 4);
                av0.x += e0.x; av0.y += e0.y; av0.z += e0.z; av0.w += e0.w;
                av1.x += e1.x; av1.y += e1.y; av1.z += e1.z; av1.w += e1.w;
            }
            bv = *(const float4*)(Bp + off * ldb);
        }
    }
#pragma unroll
    for (int p = 0; p < 8; p++) {
        int r = ty * 8 + p;
        *(float4*)&D1[(size_t)r * ldd + tx * 4] =
            make_float4(alpha * acc[p][0].f.x, alpha * acc[p][0].f.y,
                        alpha * acc[p][1].f.x, alpha * acc[p][1].f.y);
    }
}

// ---------------- 64x64 tile GEMM (R15-proven, used for D and E) ------------------
__device__ __forceinline__ void gemmKB(
    const float* __restrict__ Asrc, int lda,
    const float* __restrict__ Bsrc, int ldb,
    const float* __restrict__ Cin, int ldc,
    float* __restrict__ D1, float* __restrict__ D2, int ldd,
    int KC, float alpha, float* smf)
{
    const int tid = threadIdx.x;
    const int tx = tid & 15, ty = tid >> 4;
    const int sr = tid >> 4, sc = (tid & 15) << 2;
    const float* Ap = Asrc + (size_t)sr * lda + sc;
    const float* Bp = Bsrc + (size_t)sr * ldb + sc;
    const int nsl = KC >> 4;
    UF2 acc[4][2];
#pragma unroll
    for (int p = 0; p < 4; p++) { acc[p][0].u = 0ull; acc[p][1].u = 0ull; }

    float4 av = *(const float4*)Ap;
    float4 bv = *(const float4*)Bp;
    {
        float* A0 = smf; float* B0 = smf + 2176;
        *(float4*)&A0[sr * 136 + 2 * sc]     = make_float4(av.x, av.x, av.y, av.y);
        *(float4*)&A0[sr * 136 + 2 * sc + 4] = make_float4(av.z, av.z, av.w, av.w);
        *(float4*)&B0[sr * 68 + sc] = bv;
    }
    __syncthreads();
    if (nsl > 1) {
        av = *(const float4*)(Ap + (size_t)16 * lda);
        bv = *(const float4*)(Bp + (size_t)16 * ldb);
    }
    for (int i = 0; i < nsl; i++) {
        const float* AsD = smf + (i & 1) * 3264;
        const float* Bs  = AsD + 2176;
#pragma unroll
        for (int kk = 0; kk < 16; kk++) {
            ulonglong2 a01 = *(const ulonglong2*)&AsD[kk * 136 + ty * 8];
            ulonglong2 a23 = *(const ulonglong2*)&AsD[kk * 136 + ty * 8 + 4];
            ulonglong2 bp  = *(const ulonglong2*)&Bs[kk * 68 + tx * 4];
            ffma2(acc[0][0].u, a01.x, bp.x); ffma2(acc[0][1].u, a01.x, bp.y);
            ffma2(acc[1][0].u, a01.y, bp.x); ffma2(acc[1][1].u, a01.y, bp.y);
            ffma2(acc[2][0].u, a23.x, bp.x); ffma2(acc[2][1].u, a23.x, bp.y);
            ffma2(acc[3][0].u, a23.y, bp.x); ffma2(acc[3][1].u, a23.y, bp.y);
        }
        if (i + 1 < nsl) {
            float* An = smf + ((i + 1) & 1) * 3264;
            float* Bn = An + 2176;
            *(float4*)&An[sr * 136 + 2 * sc]     = make_float4(av.x, av.x, av.y, av.y);
            *(float4*)&An[sr * 136 + 2 * sc + 4] = make_float4(av.z, av.z, av.w, av.w);
            *(float4*)&Bn[sr * 68 + sc] = bv;
        }
        __syncthreads();
        if (i + 2 < nsl) {
            av = *(const float4*)(Ap + (size_t)(i + 2) * 16 * lda);
            bv = *(const float4*)(Bp + (size_t)(i + 2) * 16 * ldb);
        }
    }
#pragma unroll
    for (int p = 0; p < 4; p++) {
        int r = ty * 4 + p;
        float o0 = alpha * acc[p][0].f.x, o1 = alpha * acc[p][0].f.y;
        float o2 = alpha * acc[p][1].f.x, o3 = alpha * acc[p][1].f.y;
        if (Cin) {
            o0 += Cin[(size_t)r * ldc + tx * 4 + 0];
            o1 += Cin[(size_t)r * ldc + tx * 4 + 1];
            o2 += Cin[(size_t)r * ldc + tx * 4 + 2];
            o3 += Cin[(size_t)r * ldc + tx * 4 + 3];
        }
        float4 v4 = make_float4(o0, o1, o2, o3);
        *(float4*)&D1[(size_t)r * ldd + tx * 4] = v4;
        if (D2) *(float4*)&D2[(size_t)r * ldd + tx * 4] = v4;
    }
}

// ---------------- Newton-Schulz strip, resident operands (R15-proven) -------------
#define QRES_OFF 0
#define XRES_OFF 16896
#define XS_OFF   33792
#define TS_OFF   34304

__device__ __forceinline__ void newton_stage_Q(float* smf) {
    const int tid = threadIdx.x;
    float* Qres = smf + QRES_OFF;
    for (int idx = tid; idx < 4096; idx += 256) {
        int row = idx >> 5, c4 = (idx & 31) << 2;
        *(float4*)&Qres[row * 132 + c4] =
            *(const float4*)&g_Q[(size_t)(NS + row) * ND + NS + c4];
    }
}

__device__ __forceinline__ void newton_strip(const float* __restrict__ Xin,
                                             float* __restrict__ Xout, float* smf)
{
    float* Qres = smf + QRES_OFF;
    float* Xres = smf + XRES_OFF;
    float* Xs   = smf + XS_OFF;
    float* Ts   = smf + TS_OFF;
    const int tid = threadIdx.x;
    const int J = blockIdx.x * 4;
    for (int idx = tid; idx < 4096; idx += 256) {
        int row = idx >> 5, c4 = (idx & 31) << 2;
        *(float4*)&Xres[row * 132 + c4] = *(const float4*)&Xin[row * NC + c4];
    }
    for (int i = tid; i < 512; i += 256) {
        int r = i >> 2, jj = i & 3;
        Xs[i] = Xin[r * NC + J + jj];
    }
    __syncthreads();
    const int r = tid >> 1, jh = (tid & 1) * 2;
    float t0 = 0.f, t1 = 0.f;
#pragma unroll 8
    for (int k = 0; k < NC; k++) {
        float a = Qres[r * 132 + k];
        t0 = fmaf(a, Xs[k * 4 + jh], t0);
        t1 = fmaf(a, Xs[k * 4 + jh + 1], t1);
    }
    Ts[r * 4 + jh] = t0; Ts[r * 4 + jh + 1] = t1;
    __syncthreads();
    float x0 = 0.f, x1 = 0.f;
#pragma unroll 8
    for (int k = 0; k < NC; k++) {
        float a = Xres[r * 132 + k];
        x0 = fmaf(a, Ts[k * 4 + jh], x0);
        x1 = fmaf(a, Ts[k * 4 + jh + 1], x1);
    }
    Xout[r * NC + J + jh]     = 2.f * Xs[r * 4 + jh]     - x0;
    Xout[r * NC + J + jh + 1] = 2.f * Xs[r * 4 + jh + 1] - x1;
    __syncthreads();
}

// ---------------- the persistent kernel -------------------------------------------
__global__ void __launch_bounds__(256, 1) lqr_kernel(
    const float* __restrict__ F, const float* __restrict__ f,
    const float* __restrict__ C, const float* __restrict__ c,
    float* __restrict__ out)
{
    extern __shared__ __align__(16) float smf[];
    __shared__ __align__(16) float sm[3600];
    __shared__ float red[264];
    const int bid = blockIdx.x, tid = threadIdx.x, nb = gridDim.x;
    float* outK = out;
    float* outk = outK + (size_t)TT * NC * NS;
    float* outV = outk + (size_t)TT * NC;
    float* outv = outV + (size_t)TT * NS * NS;
    float* outc = outv + (size_t)TT * NS;

    // ---- init: V = C[:n,:n], v = c[:n], const = 0 ----
    for (int i = bid * 256 + tid; i < NS * NS; i += nb * 256) {
        int r = i >> 9, cq = i & (NS - 1);
        g_V[i] = C[(size_t)r * ND + cq];
    }
    if (bid == nb - 1) {
        for (int i = tid; i < NS; i += 256) g_v[i] = c[i];
        if (tid == 0) g_cst = 0.f;
    }
    gsync();

    int cur = 0;
    for (int s = 0; s < TT; s++) {
        const int t = TT - 1 - s;

        // ---- Phase A: FVt partials = V @ F, 40 tiles 128x64 x 2 k-chunks ----
        if (bid < 80) {
            const int tile = bid >> 1, chunk = bid & 1;
            const int n0 = (tile / 10) * 128, m0 = (tile % 10) * 64;
            const int kOff = chunk * 256;
            gemmBig(g_V + (size_t)kOff * NS + n0, nullptr, NS,
                    F + (size_t)kOff * ND + m0, ND,
                    g_FVp[chunk] + (size_t)n0 * ND + m0, ND,
                    256, 1.f, smf);
        } else if (bid < 144) {
            int row = (bid - 80) * 8 + (tid >> 5);
            int lane = tid & 31;
            if (row < NS) {
                float ssum = 0.f;
                for (int i = lane; i < NS; i += 32) ssum += g_V[row * NS + i] * f[i];
                for (int o = 16; o; o >>= 1) ssum += __shfl_down_sync(~0u, ssum, o);
                if (!lane) g_w[row] = ssum;
            }
        }
        gsync();

        // ---- Phase B: Q partials = FV @ F, 50 tiles 128x64 x 2 chunks; q vec ----
        if (bid < 100) {
            const int tile = bid >> 1, chunk = bid & 1;
            const int m0 = (tile / 10) * 128, n0 = (tile % 10) * 64;
            const int kOff = chunk * 256;
            gemmBig(g_FVp[0] + (size_t)kOff * ND + m0,
                    g_FVp[1] + (size_t)kOff * ND + m0, ND,
                    F + (size_t)kOff * ND + n0, ND,
                    g_Qp[chunk] + (size_t)m0 * ND + n0, ND,
                    256, 1.f, smf);
        } else if (bid < 140) {
            const int a0 = (bid - 100) * 16;
            const int ci = tid & 15, kp = tid >> 4;
            const int kb = kp * 32;
            float part = 0.f;
#pragma unroll 4
            for (int i = 0; i < 32; i++) {
                int k = kb + i;
                float fv = g_FVp[0][(size_t)k * ND + a0 + ci]
                         + g_FVp[1][(size_t)k * ND + a0 + ci];
                part += fv * f[k] + F[(size_t)k * ND + a0 + ci] * g_v[k];
            }
            sm[tid] = part;
            __syncthreads();
            if (tid < 16) {
                float ssum = 0.f;
#pragma unroll
                for (int p = 0; p < 16; p++) ssum += sm[p * 16 + tid];
                g_q[a0 + tid] = c[a0 + tid] + ssum;
            }
        }
        gsync();

        // ---- Phase Bc: Q = C + Qp0 + Qp1 (full grid, float4) ----
        {
            const float4* C4  = (const float4*)C;
            const float4* P04 = (const float4*)g_Qp[0];
            const float4* P14 = (const float4*)g_Qp[1];
            float4* Q4 = (float4*)g_Q;
            for (int i4 = bid * 256 + tid; i4 < (ND * ND) / 4; i4 += nb * 256) {
                float4 a = C4[i4], b = P04[i4], d = P14[i4];
                Q4[i4] = make_float4(a.x + b.x + d.x, a.y + b.y + d.y,
                                     a.z + b.z + d.z, a.w + b.w + d.w);
            }
        }
        gsync();

        // ---- Phase C0 (s==0): X0 = I / ||Quu||_inf ----
        if (s == 0) {
            if (bid == 0) {
                float m = 0.f;
                if (tid < NC) {
                    float ssum = 0.f;
                    const float* Qr = &g_Q[(size_t)(NS + tid) * ND + NS];
                    for (int j = 0; j < NC; j++) ssum += fabsf(Qr[j]);
                    m = ssum;
                }
                red[tid] = m; __syncthreads();
                for (int st = 128; st; st >>= 1) {
                    if (tid < st) red[tid] = fmaxf(red[tid], red[tid + st]);
                    __syncthreads();
                }
                float inv = 1.f / red[0];
                __syncthreads();
                for (int i = tid; i < NC * NC; i += 256) {
                    int r2 = i >> 7, c2 = i & 127;
                    g_X[0][i] = (r2 == c2) ? inv : 0.f;
                }
            }
            gsync();
        }

        // ---- Phase C: Newton-Schulz (warm-started), Quu resident ----
        if (bid < 32) newton_stage_Q(smf);
        int niter = (s == 0) ? 20 : ((s < 8) ? 4 : 2);
        for (int it = 0; it < niter; it++) {
            if (bid < 32) newton_strip(g_X[cur], g_X[cur ^ 1], smf);
            cur ^= 1;
            gsync();
        }

        // ---- Phase D: K = -X @ Qux (16 tiles 64x64, K=128); bid16: k, const ----
        if (bid < 16) {
            const int m0 = (bid >> 3) * 64, n0 = (bid & 7) * 64;
            gemmKB(g_X[cur] + m0, NC,
                   g_Q + (size_t)NS * ND + n0, ND,
                   nullptr, 0,
                   g_K + (size_t)m0 * NS + n0,
                   outK + (size_t)t * NC * NS + (size_t)m0 * NS + n0, NS,
                   NC, -1.f, smf);
        } else if (bid == 16) {
            float* ksh = sm; float* quk = sm + 132;
            float kv = 0.f;
            if (tid < NC) {
                const float* Xc = g_X[cur];
#pragma unroll 8
                for (int j = 0; j < NC; j++)
                    kv += Xc[(size_t)j * NC + tid] * g_q[NS + j];
                kv = -kv;
                ksh[tid] = kv; g_k[tid] = kv; outk[(size_t)t * NC + tid] = kv;
            }
            __syncthreads();
            if (tid < NC) {
                float qk = 0.f;
#pragma unroll 8
                for (int j = 0; j < NC; j++)
                    qk = fmaf(g_Q[(size_t)(NS + j) * ND + NS + tid], ksh[j], qk);
                quk[tid] = qk;
            }
            __syncthreads();
            float pp1 = 0.f, pp2 = 0.f, pp3 = 0.f, pp4 = 0.f;
            for (int i = tid; i < NC; i += 256) { pp1 += ksh[i] * quk[i]; pp2 += ksh[i] * g_q[NS + i]; }
            for (int i = tid; i < NS; i += 256) { pp3 += f[i] * g_w[i];   pp4 += f[i] * g_v[i]; }
            float parts[4] = {pp1, pp2, pp3, pp4};
            float res[4];
            for (int qd = 0; qd < 4; qd++) {
                red[tid] = parts[qd]; __syncthreads();
                for (int st = 128; st; st >>= 1) {
                    if (tid < st) red[tid] += red[tid + st];
                    __syncthreads();
                }
                res[qd] = red[0]; __syncthreads();
            }
            if (tid == 0) {
                float cn = g_cst + 0.5f * res[0] + res[1] + 0.5f * res[2] + res[3];
                g_cst = cn;
                outc[t] = cn;
            }
        }
        gsync();

        // ---- Phase E: Vn = Qxx + Qxu @ K (64 tiles 64x64, K=128); vn vector ----
        if (bid < 64) {
            const int m0 = (bid >> 3) * 64, n0 = (bid & 7) * 64;
            gemmKB(g_Q + (size_t)NS * ND + m0, ND,
                   g_K + n0, NS,
                   g_Q + (size_t)m0 * ND + n0, ND,
                   g_V + (size_t)m0 * NS + n0,
                   outV + (size_t)t * NS * NS + (size_t)m0 * NS + n0, NS,
                   NC, 1.f, smf);
        } else if (bid < 96) {
            const int x0 = (bid - 64) * 16;
            const int ci = tid & 15, jp = tid >> 4;
            float part = 0.f;
#pragma unroll
            for (int i = 0; i < 8; i++) {
                int j = jp * 8 + i;
                part += g_Q[(size_t)(NS + j) * ND + x0 + ci] * g_k[j];
            }
            sm[tid] = part;
            __syncthreads();
            if (tid < 16) {
                float ssum = 0.f;
#pragma unroll
                for (int p = 0; p < 16; p++) ssum += sm[p * 16 + tid];
                float val = g_q[x0 + tid] + ssum;
                g_v[x0 + tid] = val;
                outv[(size_t)t * NS + x0 + tid] = val;
            }
        }
        gsync();
    }
}

// ---------------- host -------------------------------------------------------------
extern "C" void kernel_launch(void* const* d_in, const int* in_sizes, int n_in,
                              void* d_out, int out_size) {
    (void)in_sizes; (void)n_in; (void)out_size;
    const float* F = (const float*)d_in[0];
    const float* f = (const float*)d_in[1];
    const float* C = (const float*)d_in[2];
    const float* c = (const float*)d_in[3];
    cudaFuncSetAttribute(lqr_kernel, cudaFuncAttributeMaxDynamicSharedMemorySize, DSMEM);
    lqr_kernel<<<NBLK, 256, DSMEM>>>(F, f, C, c, (float*)d_out);
}

// round 17
// speedup vs baseline: 1.9264x; 1.0034x over previous
#include <cuda_runtime.h>
#include <cstdint>

#define NS 512
#define NC 128
#define ND 640
#define TT 256
#define NBLK 148
#define NT 512
#define DSMEM (34816 * 4)

// ---------------- persistent device state (no allocation allowed) ----------------
__device__ __align__(16) float g_V[NS * NS];        // carry V, symmetric
__device__ __align__(16) float g_FVp[2][NS * ND];   // FVt partials (k-chunks)
__device__ __align__(16) float g_Qp[2][ND * ND];    // Q partials (k-chunks)
__device__ __align__(16) float g_Q[ND * ND];        // Q combined, symmetric
__device__ __align__(16) float g_K[NC * NS];        // K (128x512)
__device__ __align__(16) float g_X[2][NC * NC];     // Newton ping-pong
__device__ float g_q[ND], g_w[NS], g_v[NS], g_k[NC], g_cst;
__device__ unsigned g_arrive;
__device__ volatile unsigned g_gen;

// ---------------- grid-wide barrier ----------------------------------------------
__device__ __forceinline__ void gsync() {
    __syncthreads();
    if (threadIdx.x == 0) {
        unsigned gen = g_gen;
        __threadfence();
        if (atomicAdd(&g_arrive, 1u) == gridDim.x - 1) {
            g_arrive = 0;
            __threadfence();
            g_gen = gen + 1;
        } else {
            while (g_gen == gen) { __nanosleep(64); }
        }
        __threadfence();
    }
    __syncthreads();
}

// ---------------- packed f32x2 helpers --------------------------------------------
union UF2 { unsigned long long u; float2 f; };
__device__ __forceinline__ void ffma2(unsigned long long& d,
                                      unsigned long long a, unsigned long long b) {
    asm("fma.rn.f32x2 %0, %1, %2, %0;" : "+l"(d) : "l"(a), "l"(b));
}

// ---------------- 128x64 tile GEMM, 512 threads (4 rows x 4 cols / thread) --------
// D1 = alpha * sum_k (A1[k][m-win] (+A2)) * B[k][n-win].  Natural [k][col] layouts.
// Buffers at smf + b*5312: AsD[16][264] dup'd, Bs[16][68] at +4224.
__device__ __forceinline__ void gemmBig(
    const float* __restrict__ A1, const float* __restrict__ A2, int lda,
    const float* __restrict__ Bsrc, int ldb,
    float* __restrict__ D1, int ldd,
    int KC, float alpha, float* smf)
{
    const int tid = threadIdx.x;
    const int tx = tid & 15, ty = tid >> 4;          // ty 0..31
    const int srA = tid >> 5, scA = (tid & 31) << 2; // A staging: 16 x 128
    const int srB = tid >> 4, scB = (tid & 15) << 2; // B staging: 16 x 64 (tid<256)
    const bool doB = tid < 256;
    const float* Ap1 = A1 + (size_t)srA * lda + scA;
    const float* Ap2 = A2 ? (A2 + (size_t)srA * lda + scA) : (const float*)0;
    const float* Bp  = Bsrc + (size_t)srB * ldb + scB;
    const int nsl = KC >> 4;
    UF2 acc[4][2];
#pragma unroll
    for (int p = 0; p < 4; p++) { acc[p][0].u = 0ull; acc[p][1].u = 0ull; }

    float4 av = *(const float4*)Ap1;
    if (Ap2) {
        float4 e = *(const float4*)Ap2;
        av.x += e.x; av.y += e.y; av.z += e.z; av.w += e.w;
    }
    float4 bv = doB ? *(const float4*)Bp : make_float4(0.f, 0.f, 0.f, 0.f);
    {
        float* AsD = smf; float* Bs = smf + 4224;
        *(float4*)&AsD[srA * 264 + 2 * scA]     = make_float4(av.x, av.x, av.y, av.y);
        *(float4*)&AsD[srA * 264 + 2 * scA + 4] = make_float4(av.z, av.z, av.w, av.w);
        if (doB) *(float4*)&Bs[srB * 68 + scB] = bv;
    }
    __syncthreads();
    if (nsl > 1) {
        av = *(const float4*)(Ap1 + (size_t)16 * lda);
        if (Ap2) {
            float4 e = *(const float4*)(Ap2 + (size_t)16 * lda);
            av.x += e.x; av.y += e.y; av.z += e.z; av.w += e.w;
        }
        if (doB) bv = *(const float4*)(Bp + (size_t)16 * ldb);
    }
    for (int i = 0; i < nsl; i++) {
        const float* AsD = smf + (i & 1) * 5312;
        const float* Bs  = AsD + 4224;
#pragma unroll
        for (int kk = 0; kk < 16; kk++) {
            ulonglong2 a01 = *(const ulonglong2*)&AsD[kk * 264 + ty * 8];
            ulonglong2 a23 = *(const ulonglong2*)&AsD[kk * 264 + ty * 8 + 4];
            ulonglong2 bp  = *(const ulonglong2*)&Bs[kk * 68 + tx * 4];
            ffma2(acc[0][0].u, a01.x, bp.x); ffma2(acc[0][1].u, a01.x, bp.y);
            ffma2(acc[1][0].u, a01.y, bp.x); ffma2(acc[1][1].u, a01.y, bp.y);
            ffma2(acc[2][0].u, a23.x, bp.x); ffma2(acc[2][1].u, a23.x, bp.y);
            ffma2(acc[3][0].u, a23.y, bp.x); ffma2(acc[3][1].u, a23.y, bp.y);
        }
        if (i + 1 < nsl) {
            float* An = smf + ((i + 1) & 1) * 5312;
            float* Bn = An + 4224;
            *(float4*)&An[srA * 264 + 2 * scA]     = make_float4(av.x, av.x, av.y, av.y);
            *(float4*)&An[srA * 264 + 2 * scA + 4] = make_float4(av.z, av.z, av.w, av.w);
            if (doB) *(float4*)&Bn[srB * 68 + scB] = bv;
        }
        __syncthreads();
        if (i + 2 < nsl) {
            size_t off = (size_t)(i + 2) * 16;
            av = *(const float4*)(Ap1 + off * lda);
            if (Ap2) {
                float4 e = *(const float4*)(Ap2 + off * lda);
                av.x += e.x; av.y += e.y; av.z += e.z; av.w += e.w;
            }
            if (doB) bv = *(const float4*)(Bp + off * ldb);
        }
    }
#pragma unroll
    for (int p = 0; p < 4; p++) {
        int r = ty * 4 + p;
        *(float4*)&D1[(size_t)r * ldd + tx * 4] =
            make_float4(alpha * acc[p][0].f.x, alpha * acc[p][0].f.y,
                        alpha * acc[p][1].f.x, alpha * acc[p][1].f.y);
    }
}

// ---------------- 64x64 tile GEMM, 512 threads (2 rows x 4 cols / thread) ---------
__device__ __forceinline__ void gemmKB(
    const float* __restrict__ Asrc, int lda,
    const float* __restrict__ Bsrc, int ldb,
    const float* __restrict__ Cin, int ldc,
    float* __restrict__ D1, float* __restrict__ D2, int ldd,
    int KC, float alpha, float* smf)
{
    const int tid = threadIdx.x;
    const int tx = tid & 15, ty = tid >> 4;          // ty 0..31
    const int sr = tid >> 4, sc = (tid & 15) << 2;   // staging (tid<256): 16x64
    const bool doS = tid < 256;
    const float* Ap = Asrc + (size_t)sr * lda + sc;
    const float* Bp = Bsrc + (size_t)sr * ldb + sc;
    const int nsl = KC >> 4;
    UF2 acc[2][2];
#pragma unroll
    for (int p = 0; p < 2; p++) { acc[p][0].u = 0ull; acc[p][1].u = 0ull; }

    float4 av = make_float4(0.f, 0.f, 0.f, 0.f), bv = av;
    if (doS) { av = *(const float4*)Ap; bv = *(const float4*)Bp; }
    if (doS) {
        float* A0 = smf; float* B0 = smf + 2176;
        *(float4*)&A0[sr * 136 + 2 * sc]     = make_float4(av.x, av.x, av.y, av.y);
        *(float4*)&A0[sr * 136 + 2 * sc + 4] = make_float4(av.z, av.z, av.w, av.w);
        *(float4*)&B0[sr * 68 + sc] = bv;
    }
    __syncthreads();
    if (doS && nsl > 1) {
        av = *(const float4*)(Ap + (size_t)16 * lda);
        bv = *(const float4*)(Bp + (size_t)16 * ldb);
    }
    for (int i = 0; i < nsl; i++) {
        const float* AsD = smf + (i & 1) * 3264;
        const float* Bs  = AsD + 2176;
#pragma unroll
        for (int kk = 0; kk < 16; kk++) {
            ulonglong2 a01 = *(const ulonglong2*)&AsD[kk * 136 + ty * 4];
            ulonglong2 bp  = *(const ulonglong2*)&Bs[kk * 68 + tx * 4];
            ffma2(acc[0][0].u, a01.x, bp.x); ffma2(acc[0][1].u, a01.x, bp.y);
            ffma2(acc[1][0].u, a01.y, bp.x); ffma2(acc[1][1].u, a01.y, bp.y);
        }
        if (doS && i + 1 < nsl) {
            float* An = smf + ((i + 1) & 1) * 3264;
            float* Bn = An + 2176;
            *(float4*)&An[sr * 136 + 2 * sc]     = make_float4(av.x, av.x, av.y, av.y);
            *(float4*)&An[sr * 136 + 2 * sc + 4] = make_float4(av.z, av.z, av.w, av.w);
            *(float4*)&Bn[sr * 68 + sc] = bv;
        }
        __syncthreads();
        if (doS && i + 2 < nsl) {
            av = *(const float4*)(Ap + (size_t)(i + 2) * 16 * lda);
            bv = *(const float4*)(Bp + (size_t)(i + 2) * 16 * ldb);
        }
    }
#pragma unroll
    for (int p = 0; p < 2; p++) {
        int r = ty * 2 + p;
        float o0 = alpha * acc[p][0].f.x, o1 = alpha * acc[p][0].f.y;
        float o2 = alpha * acc[p][1].f.x, o3 = alpha * acc[p][1].f.y;
        if (Cin) {
            o0 += Cin[(size_t)r * ldc + tx * 4 + 0];
            o1 += Cin[(size_t)r * ldc + tx * 4 + 1];
            o2 += Cin[(size_t)r * ldc + tx * 4 + 2];
            o3 += Cin[(size_t)r * ldc + tx * 4 + 3];
        }
        float4 v4 = make_float4(o0, o1, o2, o3);
        *(float4*)&D1[(size_t)r * ldd + tx * 4] = v4;
        if (D2) *(float4*)&D2[(size_t)r * ldd + tx * 4] = v4;
    }
}

// ---------------- Newton-Schulz strip, resident operands --------------------------
#define QRES_OFF 0
#define XRES_OFF 16896
#define XS_OFF   33792
#define TS_OFF   34304

__device__ __forceinline__ void newton_stage_Q(float* smf) {
    const int tid = threadIdx.x;
    float* Qres = smf + QRES_OFF;
    for (int idx = tid; idx < 4096; idx += NT) {
        int row = idx >> 5, c4 = (idx & 31) << 2;
        *(float4*)&Qres[row * 132 + c4] =
            *(const float4*)&g_Q[(size_t)(NS + row) * ND + NS + c4];
    }
}

__device__ __forceinline__ void newton_strip(const float* __restrict__ Xin,
                                             float* __restrict__ Xout, float* smf)
{
    float* Qres = smf + QRES_OFF;
    float* Xres = smf + XRES_OFF;
    float* Xs   = smf + XS_OFF;
    float* Ts   = smf + TS_OFF;
    const int tid = threadIdx.x;
    const int J = blockIdx.x * 4;
    for (int idx = tid; idx < 4096; idx += NT) {
        int row = idx >> 5, c4 = (idx & 31) << 2;
        *(float4*)&Xres[row * 132 + c4] = *(const float4*)&Xin[row * NC + c4];
    }
    if (tid < 512) {
        int r = tid >> 2, jj = tid & 3;
        Xs[tid] = Xin[r * NC + J + jj];
    }
    __syncthreads();
    const int r = tid >> 1, jh = (tid & 1) * 2;
    float t0 = 0.f, t1 = 0.f;
    if (tid < 256) {
#pragma unroll 8
        for (int k = 0; k < NC; k++) {
            float a = Qres[r * 132 + k];
            t0 = fmaf(a, Xs[k * 4 + jh], t0);
            t1 = fmaf(a, Xs[k * 4 + jh + 1], t1);
        }
        Ts[r * 4 + jh] = t0; Ts[r * 4 + jh + 1] = t1;
    }
    __syncthreads();
    if (tid < 256) {
        float x0 = 0.f, x1 = 0.f;
#pragma unroll 8
        for (int k = 0; k < NC; k++) {
            float a = Xres[r * 132 + k];
            x0 = fmaf(a, Ts[k * 4 + jh], x0);
            x1 = fmaf(a, Ts[k * 4 + jh + 1], x1);
        }
        Xout[r * NC + J + jh]     = 2.f * Xs[r * 4 + jh]     - x0;
        Xout[r * NC + J + jh + 1] = 2.f * Xs[r * 4 + jh + 1] - x1;
    }
    __syncthreads();
}

// ---------------- the persistent kernel -------------------------------------------
__global__ void __launch_bounds__(NT, 1) lqr_kernel(
    const float* __restrict__ F, const float* __restrict__ f,
    const float* __restrict__ C, const float* __restrict__ c,
    float* __restrict__ out)
{
    extern __shared__ __align__(16) float smf[];
    __shared__ __align__(16) float sm[3600];
    __shared__ float red[520];
    const int bid = blockIdx.x, tid = threadIdx.x, nb = gridDim.x;
    float* outK = out;
    float* outk = outK + (size_t)TT * NC * NS;
    float* outV = outk + (size_t)TT * NC;
    float* outv = outV + (size_t)TT * NS * NS;
    float* outc = outv + (size_t)TT * NS;

    // ---- init: V = C[:n,:n], v = c[:n], const = 0 ----
    for (int i = bid * NT + tid; i < NS * NS; i += nb * NT) {
        int r = i >> 9, cq = i & (NS - 1);
        g_V[i] = C[(size_t)r * ND + cq];
    }
    if (bid == nb - 1) {
        if (tid < NS) g_v[tid] = c[tid];
        if (tid == 0) g_cst = 0.f;
    }
    gsync();

    int cur = 0;
    for (int s = 0; s < TT; s++) {
        const int t = TT - 1 - s;

        // ---- Phase A: FVt partials = V @ F, 40 tiles 128x64 x 2 k-chunks; w ----
        if (bid < 80) {
            const int tile = bid >> 1, chunk = bid & 1;
            const int n0 = (tile / 10) * 128, m0 = (tile % 10) * 64;
            const int kOff = chunk * 256;
            gemmBig(g_V + (size_t)kOff * NS + n0, nullptr, NS,
                    F + (size_t)kOff * ND + m0, ND,
                    g_FVp[chunk] + (size_t)n0 * ND + m0, ND,
                    256, 1.f, smf);
        } else if (bid < 112) {
            int row = (bid - 80) * 16 + (tid >> 5);
            int lane = tid & 31;
            float ssum = 0.f;
            for (int i = lane; i < NS; i += 32) ssum += g_V[row * NS + i] * f[i];
            for (int o = 16; o; o >>= 1) ssum += __shfl_down_sync(~0u, ssum, o);
            if (!lane) g_w[row] = ssum;
        }
        gsync();

        // ---- Phase B: Q partials = FV @ F, 50 tiles x 2 chunks; q vector ----
        if (bid < 100) {
            const int tile = bid >> 1, chunk = bid & 1;
            const int m0 = (tile / 10) * 128, n0 = (tile % 10) * 64;
            const int kOff = chunk * 256;
            gemmBig(g_FVp[0] + (size_t)kOff * ND + m0,
                    g_FVp[1] + (size_t)kOff * ND + m0, ND,
                    F + (size_t)kOff * ND + n0, ND,
                    g_Qp[chunk] + (size_t)m0 * ND + n0, ND,
                    256, 1.f, smf);
        } else if (bid < 140) {
            const int a0 = (bid - 100) * 16;
            const int ci = tid & 15, kp = tid >> 4;   // kp 0..31
            const int kb = kp * 16;
            float part = 0.f;
#pragma unroll 4
            for (int i = 0; i < 16; i++) {
                int k = kb + i;
                float fv = g_FVp[0][(size_t)k * ND + a0 + ci]
                         + g_FVp[1][(size_t)k * ND + a0 + ci];
                part += fv * f[k] + F[(size_t)k * ND + a0 + ci] * g_v[k];
            }
            sm[tid] = part;
            __syncthreads();
            if (tid < 16) {
                float ssum = 0.f;
#pragma unroll
                for (int p = 0; p < 32; p++) ssum += sm[p * 16 + tid];
                g_q[a0 + tid] = c[a0 + tid] + ssum;
            }
        }
        gsync();

        // ---- Phase Bc: Q = C + Qp0 + Qp1 (full grid, float4) ----
        {
            const float4* C4  = (const float4*)C;
            const float4* P04 = (const float4*)g_Qp[0];
            const float4* P14 = (const float4*)g_Qp[1];
            float4* Q4 = (float4*)g_Q;
            for (int i4 = bid * NT + tid; i4 < (ND * ND) / 4; i4 += nb * NT) {
                float4 a = C4[i4], b = P04[i4], d = P14[i4];
                Q4[i4] = make_float4(a.x + b.x + d.x, a.y + b.y + d.y,
                                     a.z + b.z + d.z, a.w + b.w + d.w);
            }
        }
        gsync();

        // ---- Phase C0 (s==0): X0 = I / ||Quu||_inf ----
        if (s == 0) {
            if (bid == 0) {
                float m = 0.f;
                if (tid < NC) {
                    float ssum = 0.f;
                    const float* Qr = &g_Q[(size_t)(NS + tid) * ND + NS];
                    for (int j = 0; j < NC; j++) ssum += fabsf(Qr[j]);
                    m = ssum;
                }
                red[tid] = m; __syncthreads();
                for (int st = 256; st; st >>= 1) {
                    if (tid < st) red[tid] = fmaxf(red[tid], red[tid + st]);
                    __syncthreads();
                }
                float inv = 1.f / red[0];
                __syncthreads();
                for (int i = tid; i < NC * NC; i += NT) {
                    int r2 = i >> 7, c2 = i & 127;
                    g_X[0][i] = (r2 == c2) ? inv : 0.f;
                }
            }
            gsync();
        }

        // ---- Phase C: Newton-Schulz (warm-started), Quu resident ----
        if (bid < 32) newton_stage_Q(smf);
        int niter = (s == 0) ? 20 : ((s < 8) ? 4 : 2);
        for (int it = 0; it < niter; it++) {
            if (bid < 32) newton_strip(g_X[cur], g_X[cur ^ 1], smf);
            cur ^= 1;
            gsync();
        }

        // ---- Phase D: K = -X @ Qux (16 tiles 64x64, K=128); bid16: k, const ----
        if (bid < 16) {
            const int m0 = (bid >> 3) * 64, n0 = (bid & 7) * 64;
            gemmKB(g_X[cur] + m0, NC,
                   g_Q + (size_t)NS * ND + n0, ND,
                   nullptr, 0,
                   g_K + (size_t)m0 * NS + n0,
                   outK + (size_t)t * NC * NS + (size_t)m0 * NS + n0, NS,
                   NC, -1.f, smf);
        } else if (bid == 16) {
            float* ksh = sm; float* quk = sm + 132;
            float kv = 0.f;
            if (tid < NC) {
                const float* Xc = g_X[cur];
#pragma unroll 8
                for (int j = 0; j < NC; j++)
                    kv += Xc[(size_t)j * NC + tid] * g_q[NS + j];
                kv = -kv;
                ksh[tid] = kv; g_k[tid] = kv; outk[(size_t)t * NC + tid] = kv;
            }
            __syncthreads();
            if (tid < NC) {
                float qk = 0.f;
#pragma unroll 8
                for (int j = 0; j < NC; j++)
                    qk = fmaf(g_Q[(size_t)(NS + j) * ND + NS + tid], ksh[j], qk);
                quk[tid] = qk;
            }
            __syncthreads();
            float pp1 = 0.f, pp2 = 0.f, pp3 = 0.f, pp4 = 0.f;
            for (int i = tid; i < NC; i += NT) { pp1 += ksh[i] * quk[i]; pp2 += ksh[i] * g_q[NS + i]; }
            for (int i = tid; i < NS; i += NT) { pp3 += f[i] * g_w[i];   pp4 += f[i] * g_v[i]; }
            float parts[4] = {pp1, pp2, pp3, pp4};
            float res[4];
            for (int qd = 0; qd < 4; qd++) {
                red[tid] = parts[qd]; __syncthreads();
                for (int st = 256; st; st >>= 1) {
                    if (tid < st) red[tid] += red[tid + st];
                    __syncthreads();
                }
                res[qd] = red[0]; __syncthreads();
            }
            if (tid == 0) {
                float cn = g_cst + 0.5f * res[0] + res[1] + 0.5f * res[2] + res[3];
                g_cst = cn;
                outc[t] = cn;
            }
        }
        gsync();

        // ---- Phase E: Vn = Qxx + Qxu @ K (64 tiles, K=128); vn over 32 CTAs ----
        if (bid < 64) {
            const int m0 = (bid >> 3) * 64, n0 = (bid & 7) * 64;
            gemmKB(g_Q + (size_t)NS * ND + m0, ND,
                   g_K + n0, NS,
                   g_Q + (size_t)m0 * ND + n0, ND,
                   g_V + (size_t)m0 * NS + n0,
                   outV + (size_t)t * NS * NS + (size_t)m0 * NS + n0, NS,
                   NC, 1.f, smf);
        } else if (bid < 96) {
            const int x0 = (bid - 64) * 16;
            const int ci = tid & 15, jp = tid >> 4;   // jp 0..31
            float part = 0.f;
#pragma unroll
            for (int i = 0; i < 4; i++) {
                int j = jp * 4 + i;
                part += g_Q[(size_t)(NS + j) * ND + x0 + ci] * g_k[j];
            }
            sm[tid] = part;
            __syncthreads();
            if (tid < 16) {
                float ssum = 0.f;
#pragma unroll
                for (int p = 0; p < 32; p++) ssum += sm[p * 16 + tid];
                float val = g_q[x0 + tid] + ssum;
                g_v[x0 + tid] = val;
                outv[(size_t)t * NS + x0 + tid] = val;
            }
        }
        gsync();
    }
}

// ---------------- host -------------------------------------------------------------
extern "C" void kernel_launch(void* const* d_in, const int* in_sizes, int n_in,
                              void* d_out, int out_size) {
    (void)in_sizes; (void)n_in; (void)out_size;
    const float* F = (const float*)d_in[0];
    const float* f = (const float*)d_in[1];
    const float* C = (const float*)d_in[2];
    const float* c = (const float*)d_in[3];
    cudaFuncSetAttribute(lqr_kernel, cudaFuncAttributeMaxDynamicSharedMemorySize, DSMEM);
    lqr_kernel<<<NBLK, NT, DSMEM>>>(F, f, C, c, (float*)d_out);
}